// round 1
// baseline (speedup 1.0000x reference)
#include <cuda_runtime.h>
#include <math.h>

#define N_TOK 4096
#define DIM   1024
#define HID   4096
#define NEXP  8
#define CAP   1280   // int(1.25 * 4096 * 2 / 8)

// ---------------- scratch (static device globals; no allocation) ----------------
__device__ float g_xbuf[(size_t)NEXP * CAP * DIM];   // gathered per-expert inputs
__device__ float g_h   [(size_t)NEXP * CAP * HID];   // hidden after gelu
__device__ float g_eout[(size_t)NEXP * CAP * DIM];   // expert outputs
__device__ int   g_expid[2 * N_TOK];                 // [k][token] -> expert
__device__ int   g_slot [2 * N_TOK];                 // [k][token] -> slot or -1 (dropped)
__device__ float g_wt   [2 * N_TOK];                 // [k][token] -> router prob

// ---------------- router: logits, top-2, softmax over top-2 ----------------
__global__ void router_kernel(const float* __restrict__ x,
                              const float* __restrict__ gw,
                              int* __restrict__ expid,
                              float* __restrict__ wt) {
    int warp = threadIdx.x >> 5, lane = threadIdx.x & 31;
    int t = blockIdx.x * 8 + warp;
    if (t >= N_TOK) return;
    const float* xr = x + (size_t)t * DIM;
    float acc[8] = {0.f,0.f,0.f,0.f,0.f,0.f,0.f,0.f};
    for (int d = lane; d < DIM; d += 32) {
        float xv = xr[d];
        const float4* g4 = (const float4*)(gw + (size_t)d * NEXP);
        float4 a = g4[0], b = g4[1];
        acc[0] += xv * a.x; acc[1] += xv * a.y; acc[2] += xv * a.z; acc[3] += xv * a.w;
        acc[4] += xv * b.x; acc[5] += xv * b.y; acc[6] += xv * b.z; acc[7] += xv * b.w;
    }
#pragma unroll
    for (int e = 0; e < 8; e++) {
#pragma unroll
        for (int o = 16; o; o >>= 1) acc[e] += __shfl_xor_sync(0xffffffffu, acc[e], o);
    }
    if (lane == 0) {
        int i0 = 0; float l0 = acc[0];
#pragma unroll
        for (int e = 1; e < 8; e++) if (acc[e] > l0) { l0 = acc[e]; i0 = e; }
        int i1 = -1; float l1 = -INFINITY;
#pragma unroll
        for (int e = 0; e < 8; e++) if (e != i0 && acc[e] > l1) { l1 = acc[e]; i1 = e; }
        float z  = expf(l1 - l0);        // <= 1
        float p0 = 1.0f / (1.0f + z);
        float p1 = z * p0;
        expid[t]         = i0;
        expid[N_TOK + t] = i1;
        wt[t]            = p0;
        wt[N_TOK + t]    = p1;
    }
}

// ---------------- deterministic slot assignment (matches serial cumsum order) ----------------
__global__ void assign_kernel(const int* __restrict__ expid, int* __restrict__ slot) {
    __shared__ int counters[NEXP];
    __shared__ int warp_hist[8][NEXP];
    int tid = threadIdx.x, lane = tid & 31, warp = tid >> 5;
    if (tid < NEXP) counters[tid] = 0;
    __syncthreads();
    for (int a = 0; a < 2 * N_TOK; a += 256) {
        int idx = a + tid;
        int e = expid[idx];
        unsigned peers = __match_any_sync(0xffffffffu, e);
        int rank = __popc(peers & ((1u << lane) - 1u));
        if (tid < 64) ((int*)warp_hist)[tid] = 0;
        __syncthreads();
        if (rank == 0) warp_hist[warp][e] = __popc(peers);
        __syncthreads();
        int base = counters[e];
#pragma unroll
        for (int w = 0; w < 8; w++) if (w < warp) base += warp_hist[w][e];
        int s = base + rank;
        slot[idx] = (s < CAP) ? s : -1;
        __syncthreads();
        if (tid < NEXP) {
            int c = counters[tid];
#pragma unroll
            for (int w = 0; w < 8; w++) c += warp_hist[w][tid];
            counters[tid] = c;
        }
        __syncthreads();
    }
}

// ---------------- gather tokens into per-expert batches ----------------
__global__ void gather_kernel(const float* __restrict__ x,
                              const int* __restrict__ expid,
                              const int* __restrict__ slot,
                              float* __restrict__ xbuf) {
    int a = blockIdx.x;
    int s = slot[a];
    if (s < 0) return;
    int e = expid[a];
    int t = a & (N_TOK - 1);
    const float4* src = (const float4*)(x + (size_t)t * DIM);
    float4* dst = (float4*)(xbuf + ((size_t)e * CAP + s) * DIM);
    dst[threadIdx.x] = src[threadIdx.x];   // 256 thr * 16B = 1024 floats
}

// ---------------- fp32 tiled GEMM: C[e] = A[e] * B[e] + bias[e], optional exact GELU ----------------
template <bool GELU>
__global__ void __launch_bounds__(256)
gemm_kernel(const float* __restrict__ A, const float* __restrict__ B,
            const float* __restrict__ bias, float* __restrict__ C,
            int K, int lda, int ldb, int ldc,
            long long sA, long long sB, long long sC, int sBias) {
    __shared__ float As[16][128];
    __shared__ float Bs[16][128];
    int e = blockIdx.z;
    A += (size_t)e * sA; B += (size_t)e * sB; C += (size_t)e * sC;
    bias += (size_t)e * sBias;
    int m0 = blockIdx.y * 128, n0 = blockIdx.x * 128;
    int tid = threadIdx.x;
    int tx = tid & 15, ty = tid >> 4;

    float acc[8][8];
#pragma unroll
    for (int i = 0; i < 8; i++)
#pragma unroll
        for (int j = 0; j < 8; j++) acc[i][j] = 0.f;

    for (int kt = 0; kt < K; kt += 16) {
#pragma unroll
        for (int r = 0; r < 2; r++) {
            int id = tid + r * 256;
            int m = id >> 2, k4 = (id & 3) * 4;
            float4 v = *(const float4*)(A + (size_t)(m0 + m) * lda + kt + k4);
            As[k4 + 0][m] = v.x; As[k4 + 1][m] = v.y;
            As[k4 + 2][m] = v.z; As[k4 + 3][m] = v.w;
        }
#pragma unroll
        for (int r = 0; r < 2; r++) {
            int id = tid + r * 256;
            int k = id >> 5, n4 = (id & 31) * 4;
            *(float4*)(&Bs[k][n4]) = *(const float4*)(B + (size_t)(kt + k) * ldb + n0 + n4);
        }
        __syncthreads();
#pragma unroll
        for (int kk = 0; kk < 16; kk++) {
            float a[8], b[8];
#pragma unroll
            for (int i = 0; i < 8; i++) a[i] = As[kk][ty * 8 + i];
#pragma unroll
            for (int j = 0; j < 8; j++) b[j] = Bs[kk][tx * 8 + j];
#pragma unroll
            for (int i = 0; i < 8; i++)
#pragma unroll
                for (int j = 0; j < 8; j++) acc[i][j] += a[i] * b[j];
        }
        __syncthreads();
    }

#pragma unroll
    for (int i = 0; i < 8; i++) {
        size_t row = (size_t)(m0 + ty * 8 + i);
#pragma unroll
        for (int j = 0; j < 8; j++) {
            int col = n0 + tx * 8 + j;
            float v = acc[i][j] + bias[col];
            if (GELU) v = 0.5f * v * (1.0f + erff(v * 0.70710678118654752f));
            C[row * ldc + col] = v;
        }
    }
}

// ---------------- combine: out[t] = sum_k w_k * exp_out[e_k][slot_k] ----------------
__global__ void combine_kernel(const int* __restrict__ expid,
                               const int* __restrict__ slot,
                               const float* __restrict__ wt,
                               const float* __restrict__ eout,
                               float* __restrict__ out) {
    int t = blockIdx.x;
    int e0 = expid[t],          s0 = slot[t];          float w0 = wt[t];
    int e1 = expid[N_TOK + t],  s1 = slot[N_TOK + t];  float w1 = wt[N_TOK + t];
    int i = threadIdx.x;
    float4 r = make_float4(0.f, 0.f, 0.f, 0.f);
    if (s0 >= 0) {
        float4 v = ((const float4*)(eout + ((size_t)e0 * CAP + s0) * DIM))[i];
        r.x += w0 * v.x; r.y += w0 * v.y; r.z += w0 * v.z; r.w += w0 * v.w;
    }
    if (s1 >= 0) {
        float4 v = ((const float4*)(eout + ((size_t)e1 * CAP + s1) * DIM))[i];
        r.x += w1 * v.x; r.y += w1 * v.y; r.z += w1 * v.z; r.w += w1 * v.w;
    }
    ((float4*)(out + (size_t)t * DIM))[i] = r;
}

// ---------------- launch ----------------
extern "C" void kernel_launch(void* const* d_in, const int* in_sizes, int n_in,
                              void* d_out, int out_size) {
    const float* x         = (const float*)d_in[0];
    const float* gate_w    = (const float*)d_in[1];
    const float* c_fc      = (const float*)d_in[2];
    const float* fc_bias   = (const float*)d_in[3];
    const float* c_proj    = (const float*)d_in[4];
    const float* proj_bias = (const float*)d_in[5];
    float* out = (float*)d_out;

    float *xbuf, *hbuf, *eout, *wt;
    int *expid, *slot;
    cudaGetSymbolAddress((void**)&xbuf,  g_xbuf);
    cudaGetSymbolAddress((void**)&hbuf,  g_h);
    cudaGetSymbolAddress((void**)&eout,  g_eout);
    cudaGetSymbolAddress((void**)&expid, g_expid);
    cudaGetSymbolAddress((void**)&slot,  g_slot);
    cudaGetSymbolAddress((void**)&wt,    g_wt);

    router_kernel<<<N_TOK / 8, 256>>>(x, gate_w, expid, wt);
    assign_kernel<<<1, 256>>>(expid, slot);
    gather_kernel<<<2 * N_TOK, 256>>>(x, expid, slot, xbuf);

    // GEMM1 + GELU: [CAP,DIM] x [DIM,HID] -> [CAP,HID]
    dim3 g1(HID / 128, CAP / 128, NEXP);
    gemm_kernel<true><<<g1, 256>>>(xbuf, c_fc, fc_bias, hbuf,
                                   DIM, DIM, HID, HID,
                                   (long long)CAP * DIM, (long long)DIM * HID,
                                   (long long)CAP * HID, HID);

    // GEMM2 + bias: [CAP,HID] x [HID,DIM] -> [CAP,DIM]
    dim3 g2(DIM / 128, CAP / 128, NEXP);
    gemm_kernel<false><<<g2, 256>>>(hbuf, c_proj, proj_bias, eout,
                                    HID, HID, DIM, DIM,
                                    (long long)CAP * HID, (long long)HID * DIM,
                                    (long long)CAP * DIM, DIM);

    combine_kernel<<<N_TOK, 256>>>(expid, slot, wt, eout, out);
}

// round 2
// speedup vs baseline: 2.5891x; 2.5891x over previous
#include <cuda_runtime.h>
#include <math.h>
#include <stdint.h>

#define N_TOK 4096
#define DIM   1024
#define HID   4096
#define NEXP  8
#define CAP   1280   // int(1.25 * 4096 * 2 / 8)

// ---------------- scratch (static device globals; no allocation) ----------------
__device__ float g_xbuf[(size_t)NEXP * CAP * DIM];   // gathered per-expert inputs
__device__ float g_h   [(size_t)NEXP * CAP * HID];   // hidden after gelu
__device__ float g_eout[(size_t)NEXP * CAP * DIM];   // expert outputs
__device__ int   g_expid[2 * N_TOK];                 // [k][token] -> expert
__device__ int   g_slot [2 * N_TOK];                 // [k][token] -> slot or -1 (dropped)
__device__ float g_wt   [2 * N_TOK];                 // [k][token] -> router prob

// ---------------- router: logits, top-2, softmax over top-2 ----------------
__global__ void router_kernel(const float* __restrict__ x,
                              const float* __restrict__ gw,
                              int* __restrict__ expid,
                              float* __restrict__ wt) {
    int warp = threadIdx.x >> 5, lane = threadIdx.x & 31;
    int t = blockIdx.x * 8 + warp;
    if (t >= N_TOK) return;
    const float* xr = x + (size_t)t * DIM;
    float acc[8] = {0.f,0.f,0.f,0.f,0.f,0.f,0.f,0.f};
    for (int d = lane; d < DIM; d += 32) {
        float xv = xr[d];
        const float4* g4 = (const float4*)(gw + (size_t)d * NEXP);
        float4 a = g4[0], b = g4[1];
        acc[0] += xv * a.x; acc[1] += xv * a.y; acc[2] += xv * a.z; acc[3] += xv * a.w;
        acc[4] += xv * b.x; acc[5] += xv * b.y; acc[6] += xv * b.z; acc[7] += xv * b.w;
    }
#pragma unroll
    for (int e = 0; e < 8; e++) {
#pragma unroll
        for (int o = 16; o; o >>= 1) acc[e] += __shfl_xor_sync(0xffffffffu, acc[e], o);
    }
    if (lane == 0) {
        int i0 = 0; float l0 = acc[0];
#pragma unroll
        for (int e = 1; e < 8; e++) if (acc[e] > l0) { l0 = acc[e]; i0 = e; }
        int i1 = -1; float l1 = -INFINITY;
#pragma unroll
        for (int e = 0; e < 8; e++) if (e != i0 && acc[e] > l1) { l1 = acc[e]; i1 = e; }
        float z  = expf(l1 - l0);        // <= 1
        float p0 = 1.0f / (1.0f + z);
        float p1 = z * p0;
        expid[t]         = i0;
        expid[N_TOK + t] = i1;
        wt[t]            = p0;
        wt[N_TOK + t]    = p1;
    }
}

// ---------------- deterministic slot assignment (matches serial cumsum order) ----------------
__global__ void assign_kernel(const int* __restrict__ expid, int* __restrict__ slot) {
    __shared__ int counters[NEXP];
    __shared__ int warp_hist[8][NEXP];
    int tid = threadIdx.x, lane = tid & 31, warp = tid >> 5;
    if (tid < NEXP) counters[tid] = 0;
    __syncthreads();
    for (int a = 0; a < 2 * N_TOK; a += 256) {
        int idx = a + tid;
        int e = expid[idx];
        unsigned peers = __match_any_sync(0xffffffffu, e);
        int rank = __popc(peers & ((1u << lane) - 1u));
        if (tid < 64) ((int*)warp_hist)[tid] = 0;
        __syncthreads();
        if (rank == 0) warp_hist[warp][e] = __popc(peers);
        __syncthreads();
        int base = counters[e];
#pragma unroll
        for (int w = 0; w < 8; w++) if (w < warp) base += warp_hist[w][e];
        int s = base + rank;
        slot[idx] = (s < CAP) ? s : -1;
        __syncthreads();
        if (tid < NEXP) {
            int c = counters[tid];
#pragma unroll
            for (int w = 0; w < 8; w++) c += warp_hist[w][tid];
            counters[tid] = c;
        }
        __syncthreads();
    }
}

// ---------------- gather tokens into per-expert batches ----------------
__global__ void gather_kernel(const float* __restrict__ x,
                              const int* __restrict__ expid,
                              const int* __restrict__ slot,
                              float* __restrict__ xbuf) {
    int a = blockIdx.x;
    int s = slot[a];
    if (s < 0) return;
    int e = expid[a];
    int t = a & (N_TOK - 1);
    const float4* src = (const float4*)(x + (size_t)t * DIM);
    float4* dst = (float4*)(xbuf + ((size_t)e * CAP + s) * DIM);
    dst[threadIdx.x] = src[threadIdx.x];   // 256 thr * 16B = 1024 floats
}

// ---------------- tf32 tensor-core GEMM ----------------
__device__ __forceinline__ float to_tf32(float x) {
    float r; asm("cvt.rna.tf32.f32 %0, %1;" : "=f"(r) : "f"(x)); return r;
}

__device__ __forceinline__ void mma8(float d[4], const float a[4], const float b[2]) {
    const uint32_t* A = (const uint32_t*)a;
    const uint32_t* B = (const uint32_t*)b;
    asm volatile(
        "mma.sync.aligned.m16n8k8.row.col.f32.tf32.tf32.f32 "
        "{%0,%1,%2,%3},{%4,%5,%6,%7},{%8,%9},{%0,%1,%2,%3};"
        : "+f"(d[0]), "+f"(d[1]), "+f"(d[2]), "+f"(d[3])
        : "r"(A[0]), "r"(A[1]), "r"(A[2]), "r"(A[3]), "r"(B[0]), "r"(B[1]));
}

// C[e] = A[e] (MxK, row-major) * B[e] (KxN, row-major) + bias[e], optional exact GELU.
// Block tile 128x128, K-tile 16, 8 warps of 64x32 warp tiles, double-buffered smem.
template <bool GELU>
__global__ void __launch_bounds__(256)
gemm_tc(const float* __restrict__ A, const float* __restrict__ B,
        const float* __restrict__ bias, float* __restrict__ C,
        int K, int lda, int ldb, int ldc,
        long long sA, long long sB, long long sC, int sBias) {
    // A stored transposed [k][m] (stride 132 -> frag-load bank = 4*qd+grp, conflict-free)
    // B stored [k][n]            (stride 136 -> frag-load bank = 8*qd+grp, conflict-free)
    __shared__ __align__(16) float As[2][16][132];
    __shared__ __align__(16) float Bs[2][16][136];

    const int e = blockIdx.z;
    A += (size_t)e * sA; B += (size_t)e * sB; C += (size_t)e * sC;
    bias += (size_t)e * sBias;
    const int m0 = blockIdx.y * 128, n0 = blockIdx.x * 128;

    const int tid  = threadIdx.x;
    const int lane = tid & 31, wid = tid >> 5;
    const int wm = (wid & 1) * 64;        // warp row offset within block tile
    const int wn = (wid >> 1) * 32;       // warp col offset
    const int grp = lane >> 2, qd = lane & 3;

    // global-load assignment
    const int ar0 = tid >> 2;             // A row (0..63), +64 for i=1
    const int ak0 = (tid & 3) * 4;        // A k offset (0,4,8,12)
    const int br0 = tid >> 5;             // B k row (0..7), +8 for i=1
    const int bc0 = (tid & 31) * 4;       // B col

    float4 pa[2], pb[2];
    float acc[4][4][4];
#pragma unroll
    for (int i = 0; i < 4; i++)
#pragma unroll
        for (int j = 0; j < 4; j++)
#pragma unroll
            for (int r = 0; r < 4; r++) acc[i][j][r] = 0.f;

    const int NK = K >> 4;

#define LOAD_TILE(kt)                                                              \
    do {                                                                           \
        _Pragma("unroll") for (int i = 0; i < 2; i++) {                            \
            pa[i] = *(const float4*)(A + (size_t)(m0 + ar0 + i * 64) * lda +       \
                                     (kt) * 16 + ak0);                             \
            pb[i] = *(const float4*)(B + (size_t)((kt) * 16 + br0 + i * 8) * ldb + \
                                     n0 + bc0);                                    \
        }                                                                          \
    } while (0)

#define STORE_TILE(buf)                                                \
    do {                                                               \
        _Pragma("unroll") for (int i = 0; i < 2; i++) {                \
            int r = ar0 + i * 64;                                      \
            As[buf][ak0 + 0][r] = to_tf32(pa[i].x);                    \
            As[buf][ak0 + 1][r] = to_tf32(pa[i].y);                    \
            As[buf][ak0 + 2][r] = to_tf32(pa[i].z);                    \
            As[buf][ak0 + 3][r] = to_tf32(pa[i].w);                    \
            float4 t;                                                  \
            t.x = to_tf32(pb[i].x); t.y = to_tf32(pb[i].y);            \
            t.z = to_tf32(pb[i].z); t.w = to_tf32(pb[i].w);            \
            *(float4*)&Bs[buf][br0 + i * 8][bc0] = t;                  \
        }                                                              \
    } while (0)

#define COMPUTE(buf)                                                        \
    do {                                                                    \
        _Pragma("unroll") for (int ks = 0; ks < 2; ks++) {                  \
            const int kb = ks * 8;                                          \
            float a[4][4], b[4][2];                                         \
            _Pragma("unroll") for (int mt = 0; mt < 4; mt++) {              \
                int row = wm + mt * 16 + grp;                               \
                a[mt][0] = As[buf][kb + qd][row];                           \
                a[mt][1] = As[buf][kb + qd][row + 8];                       \
                a[mt][2] = As[buf][kb + qd + 4][row];                       \
                a[mt][3] = As[buf][kb + qd + 4][row + 8];                   \
            }                                                               \
            _Pragma("unroll") for (int nt = 0; nt < 4; nt++) {              \
                int col = wn + nt * 8 + grp;                                \
                b[nt][0] = Bs[buf][kb + qd][col];                           \
                b[nt][1] = Bs[buf][kb + qd + 4][col];                       \
            }                                                               \
            _Pragma("unroll") for (int mt = 0; mt < 4; mt++)                \
                _Pragma("unroll") for (int nt = 0; nt < 4; nt++)            \
                    mma8(acc[mt][nt], a[mt], b[nt]);                        \
        }                                                                   \
    } while (0)

    LOAD_TILE(0);
    STORE_TILE(0);
    __syncthreads();
    for (int kt = 0; kt < NK; kt++) {
        int cur = kt & 1;
        if (kt + 1 < NK) LOAD_TILE(kt + 1);
        COMPUTE(cur);
        if (kt + 1 < NK) STORE_TILE(cur ^ 1);
        __syncthreads();
    }

#undef LOAD_TILE
#undef STORE_TILE
#undef COMPUTE

    // epilogue: bias (+ exact GELU), vectorized 8B stores
#pragma unroll
    for (int mt = 0; mt < 4; mt++) {
#pragma unroll
        for (int nt = 0; nt < 4; nt++) {
            int col = n0 + wn + nt * 8 + qd * 2;
            float b0 = bias[col], b1 = bias[col + 1];
#pragma unroll
            for (int h = 0; h < 2; h++) {
                size_t row = (size_t)(m0 + wm + mt * 16 + grp + h * 8);
                float v0 = acc[mt][nt][h * 2 + 0] + b0;
                float v1 = acc[mt][nt][h * 2 + 1] + b1;
                if (GELU) {
                    v0 = 0.5f * v0 * (1.0f + erff(v0 * 0.70710678118654752f));
                    v1 = 0.5f * v1 * (1.0f + erff(v1 * 0.70710678118654752f));
                }
                float2 o = make_float2(v0, v1);
                *(float2*)(C + row * ldc + col) = o;
            }
        }
    }
}

// ---------------- combine: out[t] = sum_k w_k * exp_out[e_k][slot_k] ----------------
__global__ void combine_kernel(const int* __restrict__ expid,
                               const int* __restrict__ slot,
                               const float* __restrict__ wt,
                               const float* __restrict__ eout,
                               float* __restrict__ out) {
    int t = blockIdx.x;
    int e0 = expid[t],          s0 = slot[t];          float w0 = wt[t];
    int e1 = expid[N_TOK + t],  s1 = slot[N_TOK + t];  float w1 = wt[N_TOK + t];
    int i = threadIdx.x;
    float4 r = make_float4(0.f, 0.f, 0.f, 0.f);
    if (s0 >= 0) {
        float4 v = ((const float4*)(eout + ((size_t)e0 * CAP + s0) * DIM))[i];
        r.x += w0 * v.x; r.y += w0 * v.y; r.z += w0 * v.z; r.w += w0 * v.w;
    }
    if (s1 >= 0) {
        float4 v = ((const float4*)(eout + ((size_t)e1 * CAP + s1) * DIM))[i];
        r.x += w1 * v.x; r.y += w1 * v.y; r.z += w1 * v.z; r.w += w1 * v.w;
    }
    ((float4*)(out + (size_t)t * DIM))[i] = r;
}

// ---------------- launch ----------------
extern "C" void kernel_launch(void* const* d_in, const int* in_sizes, int n_in,
                              void* d_out, int out_size) {
    const float* x         = (const float*)d_in[0];
    const float* gate_w    = (const float*)d_in[1];
    const float* c_fc      = (const float*)d_in[2];
    const float* fc_bias   = (const float*)d_in[3];
    const float* c_proj    = (const float*)d_in[4];
    const float* proj_bias = (const float*)d_in[5];
    float* out = (float*)d_out;

    float *xbuf, *hbuf, *eout, *wt;
    int *expid, *slot;
    cudaGetSymbolAddress((void**)&xbuf,  g_xbuf);
    cudaGetSymbolAddress((void**)&hbuf,  g_h);
    cudaGetSymbolAddress((void**)&eout,  g_eout);
    cudaGetSymbolAddress((void**)&expid, g_expid);
    cudaGetSymbolAddress((void**)&slot,  g_slot);
    cudaGetSymbolAddress((void**)&wt,    g_wt);

    router_kernel<<<N_TOK / 8, 256>>>(x, gate_w, expid, wt);
    assign_kernel<<<1, 256>>>(expid, slot);
    gather_kernel<<<2 * N_TOK, 256>>>(x, expid, slot, xbuf);

    // GEMM1 + GELU: [CAP,DIM] x [DIM,HID] -> [CAP,HID]
    dim3 g1(HID / 128, CAP / 128, NEXP);
    gemm_tc<true><<<g1, 256>>>(xbuf, c_fc, fc_bias, hbuf,
                               DIM, DIM, HID, HID,
                               (long long)CAP * DIM, (long long)DIM * HID,
                               (long long)CAP * HID, HID);

    // GEMM2 + bias: [CAP,HID] x [HID,DIM] -> [CAP,DIM]
    dim3 g2(DIM / 128, CAP / 128, NEXP);
    gemm_tc<false><<<g2, 256>>>(hbuf, c_proj, proj_bias, eout,
                                HID, HID, DIM, DIM,
                                (long long)CAP * HID, (long long)HID * DIM,
                                (long long)CAP * DIM, DIM);

    combine_kernel<<<N_TOK, 256>>>(expid, slot, wt, eout, out);
}

// round 4
// speedup vs baseline: 3.2187x; 1.2432x over previous
#include <cuda_runtime.h>
#include <math.h>
#include <stdint.h>

#define N_TOK 4096
#define DIM   1024
#define HID   4096
#define NEXP  8
#define CAP   1280   // int(1.25 * 4096 * 2 / 8)

// ---------------- scratch (static device globals; no allocation) ----------------
__device__ float g_xbuf[(size_t)NEXP * CAP * DIM];   // gathered per-expert inputs (tf32-rounded)
__device__ float g_h   [(size_t)NEXP * CAP * HID];   // hidden after gelu (tf32-rounded)
__device__ float g_eout[(size_t)NEXP * CAP * DIM];   // expert outputs (fp32)
__device__ int   g_expid[2 * N_TOK];
__device__ int   g_slot [2 * N_TOK];
__device__ float g_wtp  [2 * N_TOK];

__device__ __forceinline__ float to_tf32(float x) {
    float r; asm("cvt.rna.tf32.f32 %0, %1;" : "=f"(r) : "f"(x)); return r;
}
__device__ __forceinline__ uint32_t smem_to_u32(const void* p) {
    uint32_t a;
    asm("{ .reg .u64 t; cvta.to.shared.u64 t, %1; cvt.u32.u64 %0, t; }" : "=r"(a) : "l"(p));
    return a;
}
#define CP_ASYNC16(dst, src) \
    asm volatile("cp.async.cg.shared.global [%0], [%1], 16;\n" :: "r"(dst), "l"(src))
#define CP_COMMIT() asm volatile("cp.async.commit_group;\n" ::: "memory")
#define CP_WAIT1()  asm volatile("cp.async.wait_group 1;\n" ::: "memory")

__device__ __forceinline__ void mma8(float d[4], const float a[4], const float b[2]) {
    const uint32_t* A = (const uint32_t*)a;
    const uint32_t* B = (const uint32_t*)b;
    asm volatile(
        "mma.sync.aligned.m16n8k8.row.col.f32.tf32.tf32.f32 "
        "{%0,%1,%2,%3},{%4,%5,%6,%7},{%8,%9},{%0,%1,%2,%3};"
        : "+f"(d[0]), "+f"(d[1]), "+f"(d[2]), "+f"(d[3])
        : "r"(A[0]), "r"(A[1]), "r"(A[2]), "r"(A[3]), "r"(B[0]), "r"(B[1]));
}

// ---------------- router ----------------
__global__ void router_kernel(const float* __restrict__ x,
                              const float* __restrict__ gw,
                              int* __restrict__ expid,
                              float* __restrict__ wt) {
    int warp = threadIdx.x >> 5, lane = threadIdx.x & 31;
    int t = blockIdx.x * 8 + warp;
    if (t >= N_TOK) return;
    const float* xr = x + (size_t)t * DIM;
    float acc[8] = {0.f,0.f,0.f,0.f,0.f,0.f,0.f,0.f};
    for (int d = lane; d < DIM; d += 32) {
        float xv = xr[d];
        const float4* g4 = (const float4*)(gw + (size_t)d * NEXP);
        float4 a = g4[0], b = g4[1];
        acc[0] += xv * a.x; acc[1] += xv * a.y; acc[2] += xv * a.z; acc[3] += xv * a.w;
        acc[4] += xv * b.x; acc[5] += xv * b.y; acc[6] += xv * b.z; acc[7] += xv * b.w;
    }
#pragma unroll
    for (int e = 0; e < 8; e++)
#pragma unroll
        for (int o = 16; o; o >>= 1) acc[e] += __shfl_xor_sync(0xffffffffu, acc[e], o);
    if (lane == 0) {
        int i0 = 0; float l0 = acc[0];
#pragma unroll
        for (int e = 1; e < 8; e++) if (acc[e] > l0) { l0 = acc[e]; i0 = e; }
        int i1 = -1; float l1 = -INFINITY;
#pragma unroll
        for (int e = 0; e < 8; e++) if (e != i0 && acc[e] > l1) { l1 = acc[e]; i1 = e; }
        float z  = expf(l1 - l0);
        float p0 = 1.0f / (1.0f + z);
        expid[t]         = i0;
        expid[N_TOK + t] = i1;
        wt[t]            = p0;
        wt[N_TOK + t]    = z * p0;
    }
}

// ---------------- deterministic slot assignment ----------------
__global__ void assign_kernel(const int* __restrict__ expid, int* __restrict__ slot) {
    __shared__ int counters[NEXP];
    __shared__ int warp_hist[8][NEXP];
    int tid = threadIdx.x, lane = tid & 31, warp = tid >> 5;
    if (tid < NEXP) counters[tid] = 0;
    __syncthreads();
    for (int a = 0; a < 2 * N_TOK; a += 256) {
        int idx = a + tid;
        int e = expid[idx];
        unsigned peers = __match_any_sync(0xffffffffu, e);
        int rank = __popc(peers & ((1u << lane) - 1u));
        if (tid < 64) ((int*)warp_hist)[tid] = 0;
        __syncthreads();
        if (rank == 0) warp_hist[warp][e] = __popc(peers);
        __syncthreads();
        int base = counters[e];
#pragma unroll
        for (int w = 0; w < 8; w++) if (w < warp) base += warp_hist[w][e];
        int s = base + rank;
        slot[idx] = (s < CAP) ? s : -1;
        __syncthreads();
        if (tid < NEXP) {
            int c = counters[tid];
#pragma unroll
            for (int w = 0; w < 8; w++) c += warp_hist[w][tid];
            counters[tid] = c;
        }
        __syncthreads();
    }
}

// ---------------- gather (writes tf32-rounded) ----------------
__global__ void gather_kernel(const float* __restrict__ x,
                              const int* __restrict__ expid,
                              const int* __restrict__ slot,
                              float* __restrict__ xbuf) {
    int a = blockIdx.x;
    int s = slot[a];
    if (s < 0) return;
    int e = expid[a];
    int t = a & (N_TOK - 1);
    const float4* src = (const float4*)(x + (size_t)t * DIM);
    float4* dst = (float4*)(xbuf + ((size_t)e * CAP + s) * DIM);
    float4 v = src[threadIdx.x];
    v.x = to_tf32(v.x); v.y = to_tf32(v.y); v.z = to_tf32(v.z); v.w = to_tf32(v.w);
    dst[threadIdx.x] = v;
}

// ============ tf32 mma.sync GEMM, cp.async 3-stage pipeline ============
// A: [M,K] row-major, values ALREADY tf32-rounded in gmem (copied raw via cp.async).
// B: [K,N] row-major fp32 weights, rounded with cvt.rna during STS.
// Block tile 128x128, ktile 16, 8 warps of 64x32 (m16n8k8).
// Smem: A [128][20] fp32 (pad 4 -> LDS bank 20*grp+qd covers all 32), x3 stages
//       B [16][136]  fp32 (pad 8 -> LDS bank 8*qd+grp distinct),      x3 stages
#define A_STAGE_W 2560   // 128*20 words
#define B_STAGE_W 2176   // 16*136 words
#define SMEM_W    (3 * A_STAGE_W + 3 * B_STAGE_W)   // 14208 words = 56832 B

template <bool GELU>
__global__ void __launch_bounds__(256, 2)
gemm_cp(const float* __restrict__ A, const float* __restrict__ B,
        const float* __restrict__ bias, float* __restrict__ C,
        int K, int ldb, int ldc,
        long long sA, long long sB, long long sC, int sBias, int NK) {
    extern __shared__ __align__(16) float smemF[];
    const uint32_t sbase = smem_to_u32(smemF);

    const int e = blockIdx.z;
    A    += (size_t)e * sA;
    B    += (size_t)e * sB;
    C    += (size_t)e * sC;
    bias += (size_t)e * sBias;
    const int m0 = blockIdx.y * 128, n0 = blockIdx.x * 128;

    const int tid = threadIdx.x, lane = tid & 31, wid = tid >> 5;
    const int wm = (wid & 1) * 64;
    const int wn = (wid >> 1) * 32;
    const int grp = lane >> 2, qd = lane & 3;

    // --- A cp.async params: id = tid + 256r -> row=id>>2 (0..127), chunk=id&3
    const int rowA = tid >> 2, chA = tid & 3;
    const float* srcA = A + (size_t)(m0 + rowA) * K + chA * 4;
    const uint32_t dstA = sbase + (uint32_t)(rowA * 80 + chA * 16);

    // --- B ldg/sts params: id = tid + 256r -> k=id>>5 (0..15), n4=(id&31)*4
    const int kB = tid >> 5, nB = (tid & 31) * 4;
    const float* srcB = B + (size_t)kB * ldb + n0 + nB;
    float* dstB = smemF + 3 * A_STAGE_W + kB * 136 + nB;

    float4 pb0, pb1;

#define CPA(kt, st)                                                          \
    do {                                                                     \
        uint32_t d_ = dstA + (uint32_t)(st) * (A_STAGE_W * 4);               \
        const float* s_ = srcA + (size_t)(kt) * 16;                          \
        CP_ASYNC16(d_, s_);                                                  \
        CP_ASYNC16(d_ + 64 * 80, s_ + (size_t)64 * K);                       \
    } while (0)
#define LDGB(kt)                                                             \
    do {                                                                     \
        pb0 = *(const float4*)(srcB + (size_t)(kt) * 16 * ldb);              \
        pb1 = *(const float4*)(srcB + (size_t)((kt) * 16 + 8) * ldb);        \
    } while (0)
#define STSB(st)                                                             \
    do {                                                                     \
        float* d_ = dstB + (st) * B_STAGE_W;                                 \
        float4 t0, t1;                                                       \
        t0.x = to_tf32(pb0.x); t0.y = to_tf32(pb0.y);                        \
        t0.z = to_tf32(pb0.z); t0.w = to_tf32(pb0.w);                        \
        t1.x = to_tf32(pb1.x); t1.y = to_tf32(pb1.y);                        \
        t1.z = to_tf32(pb1.z); t1.w = to_tf32(pb1.w);                        \
        *(float4*)d_ = t0;                                                   \
        *(float4*)(d_ + 8 * 136) = t1;                                       \
    } while (0)

    float acc[4][4][4];
#pragma unroll
    for (int i = 0; i < 4; i++)
#pragma unroll
        for (int j = 0; j < 4; j++)
#pragma unroll
            for (int r = 0; r < 4; r++) acc[i][j][r] = 0.f;

#define COMPUTE(st)                                                          \
    do {                                                                     \
        const float* aS = smemF + (st) * A_STAGE_W;                          \
        const float* bS = smemF + 3 * A_STAGE_W + (st) * B_STAGE_W;          \
        _Pragma("unroll") for (int ks = 0; ks < 2; ks++) {                   \
            const int kb = ks * 8;                                           \
            float a[4][4], b[4][2];                                          \
            _Pragma("unroll") for (int mt = 0; mt < 4; mt++) {               \
                const float* ap = aS + (wm + mt * 16 + grp) * 20 + kb + qd;  \
                a[mt][0] = ap[0];                                            \
                a[mt][1] = ap[160];                                          \
                a[mt][2] = ap[4];                                            \
                a[mt][3] = ap[164];                                          \
            }                                                                \
            _Pragma("unroll") for (int nt = 0; nt < 4; nt++) {               \
                const float* bp = bS + (kb + qd) * 136 + wn + nt * 8 + grp;  \
                b[nt][0] = bp[0];                                            \
                b[nt][1] = bp[544];                                          \
            }                                                                \
            _Pragma("unroll") for (int mt = 0; mt < 4; mt++)                 \
                _Pragma("unroll") for (int nt = 0; nt < 4; nt++)             \
                    mma8(acc[mt][nt], a[mt], b[nt]);                         \
        }                                                                    \
    } while (0)

    // ---- prologue: stages 0,1 ----
    CPA(0, 0); CP_COMMIT();
    CPA(1, 1); CP_COMMIT();
    LDGB(0); STSB(0);
    LDGB(1); STSB(1);
    CP_WAIT1();
    __syncthreads();

    int stage = 0;
    for (int kt = 0; kt < NK; kt++) {
        const bool pre = (kt + 2 < NK);
        int ns = stage + 2; if (ns >= 3) ns -= 3;
        if (pre) { LDGB(kt + 2); CPA(kt + 2, ns); }
        CP_COMMIT();
        COMPUTE(stage);
        if (pre) STSB(ns);
        CP_WAIT1();
        __syncthreads();
        if (++stage == 3) stage = 0;
    }
#undef CPA
#undef LDGB
#undef STSB
#undef COMPUTE

    // ---- epilogue: bias (+ exact GELU, tf32-rounded for GEMM1 output) ----
#pragma unroll
    for (int mt = 0; mt < 4; mt++) {
#pragma unroll
        for (int nt = 0; nt < 4; nt++) {
            int col = n0 + wn + nt * 8 + qd * 2;
            float b0 = bias[col], b1 = bias[col + 1];
#pragma unroll
            for (int h = 0; h < 2; h++) {
                size_t row = (size_t)(m0 + wm + mt * 16 + grp + h * 8);
                float v0 = acc[mt][nt][h * 2 + 0] + b0;
                float v1 = acc[mt][nt][h * 2 + 1] + b1;
                if (GELU) {
                    v0 = to_tf32(0.5f * v0 * (1.0f + erff(v0 * 0.70710678118654752f)));
                    v1 = to_tf32(0.5f * v1 * (1.0f + erff(v1 * 0.70710678118654752f)));
                }
                *(float2*)(C + row * ldc + col) = make_float2(v0, v1);
            }
        }
    }
}

// ---------------- combine ----------------
__global__ void combine_kernel(const int* __restrict__ expid,
                               const int* __restrict__ slot,
                               const float* __restrict__ wt,
                               const float* __restrict__ eout,
                               float* __restrict__ out) {
    int t = blockIdx.x;
    int e0 = expid[t],          s0 = slot[t];          float w0 = wt[t];
    int e1 = expid[N_TOK + t],  s1 = slot[N_TOK + t];  float w1 = wt[N_TOK + t];
    int i = threadIdx.x;
    float4 r = make_float4(0.f, 0.f, 0.f, 0.f);
    if (s0 >= 0) {
        float4 v = ((const float4*)(eout + ((size_t)e0 * CAP + s0) * DIM))[i];
        r.x += w0 * v.x; r.y += w0 * v.y; r.z += w0 * v.z; r.w += w0 * v.w;
    }
    if (s1 >= 0) {
        float4 v = ((const float4*)(eout + ((size_t)e1 * CAP + s1) * DIM))[i];
        r.x += w1 * v.x; r.y += w1 * v.y; r.z += w1 * v.z; r.w += w1 * v.w;
    }
    ((float4*)(out + (size_t)t * DIM))[i] = r;
}

// ---------------- launch ----------------
extern "C" void kernel_launch(void* const* d_in, const int* in_sizes, int n_in,
                              void* d_out, int out_size) {
    const float* x         = (const float*)d_in[0];
    const float* gate_w    = (const float*)d_in[1];
    const float* c_fc      = (const float*)d_in[2];
    const float* fc_bias   = (const float*)d_in[3];
    const float* c_proj    = (const float*)d_in[4];
    const float* proj_bias = (const float*)d_in[5];
    float* out = (float*)d_out;

    float *xbuf, *hbuf, *eout, *wt;
    int *expid, *slot;
    cudaGetSymbolAddress((void**)&xbuf,  g_xbuf);
    cudaGetSymbolAddress((void**)&hbuf,  g_h);
    cudaGetSymbolAddress((void**)&eout,  g_eout);
    cudaGetSymbolAddress((void**)&expid, g_expid);
    cudaGetSymbolAddress((void**)&slot,  g_slot);
    cudaGetSymbolAddress((void**)&wt,    g_wtp);

    const int smem_bytes = SMEM_W * 4;
    cudaFuncSetAttribute(gemm_cp<true>,  cudaFuncAttributeMaxDynamicSharedMemorySize, smem_bytes);
    cudaFuncSetAttribute(gemm_cp<false>, cudaFuncAttributeMaxDynamicSharedMemorySize, smem_bytes);

    router_kernel<<<N_TOK / 8, 256>>>(x, gate_w, expid, wt);
    assign_kernel<<<1, 256>>>(expid, slot);
    gather_kernel<<<2 * N_TOK, 256>>>(x, expid, slot, xbuf);

    // GEMM1 + GELU: [CAP,DIM] x [DIM,HID] -> [CAP,HID]
    dim3 g1(HID / 128, CAP / 128, NEXP);
    gemm_cp<true><<<g1, 256, smem_bytes>>>(xbuf, c_fc, fc_bias, hbuf,
                                           DIM, HID, HID,
                                           (long long)CAP * DIM, (long long)DIM * HID,
                                           (long long)CAP * HID, HID, DIM / 16);

    // GEMM2 + bias: [CAP,HID] x [HID,DIM] -> [CAP,DIM]
    dim3 g2(DIM / 128, CAP / 128, NEXP);
    gemm_cp<false><<<g2, 256, smem_bytes>>>(hbuf, c_proj, proj_bias, eout,
                                            HID, DIM, DIM,
                                            (long long)CAP * HID, (long long)HID * DIM,
                                            (long long)CAP * DIM, DIM, HID / 16);

    combine_kernel<<<N_TOK, 256>>>(expid, slot, wt, eout, out);
}

// round 5
// speedup vs baseline: 3.6774x; 1.1425x over previous
#include <cuda_runtime.h>
#include <math.h>
#include <stdint.h>

#define N_TOK 4096
#define DIM   1024
#define HID   4096
#define NEXP  8
#define CAP   1280   // int(1.25 * 4096 * 2 / 8)

// ---------------- scratch (static device globals; no allocation) ----------------
__device__ float g_xbuf[(size_t)NEXP * CAP * DIM];   // gathered per-expert inputs (tf32-rounded)
__device__ float g_h   [(size_t)NEXP * CAP * HID];   // hidden after gelu (tf32-rounded)
__device__ float g_eout[(size_t)NEXP * CAP * DIM];   // expert outputs (fp32)
__device__ float g_wr1 [(size_t)NEXP * DIM * HID];   // c_fc   tf32-rounded
__device__ float g_wr2 [(size_t)NEXP * HID * DIM];   // c_proj tf32-rounded
__device__ int   g_expid[2 * N_TOK];
__device__ int   g_slot [2 * N_TOK];
__device__ float g_wtp  [2 * N_TOK];

__device__ __forceinline__ float to_tf32(float x) {
    float r; asm("cvt.rna.tf32.f32 %0, %1;" : "=f"(r) : "f"(x)); return r;
}
__device__ __forceinline__ uint32_t smem_to_u32(const void* p) {
    uint32_t a;
    asm("{ .reg .u64 t; cvta.to.shared.u64 t, %1; cvt.u32.u64 %0, t; }" : "=r"(a) : "l"(p));
    return a;
}
#define CP_ASYNC16(dst, src) \
    asm volatile("cp.async.cg.shared.global [%0], [%1], 16;\n" :: "r"(dst), "l"(src))
#define CP_COMMIT() asm volatile("cp.async.commit_group;\n" ::: "memory")
#define CP_WAIT2()  asm volatile("cp.async.wait_group 2;\n" ::: "memory")

__device__ __forceinline__ void mma8(float d[4], const float a[4], const float b[2]) {
    const uint32_t* A = (const uint32_t*)a;
    const uint32_t* B = (const uint32_t*)b;
    asm volatile(
        "mma.sync.aligned.m16n8k8.row.col.f32.tf32.tf32.f32 "
        "{%0,%1,%2,%3},{%4,%5,%6,%7},{%8,%9},{%0,%1,%2,%3};"
        : "+f"(d[0]), "+f"(d[1]), "+f"(d[2]), "+f"(d[3])
        : "r"(A[0]), "r"(A[1]), "r"(A[2]), "r"(A[3]), "r"(B[0]), "r"(B[1]));
}

// ---------------- elementwise tf32 rounding of weights ----------------
__global__ void round_kernel(const float* __restrict__ W, float* __restrict__ R) {
    size_t i = ((size_t)blockIdx.x * 256 + threadIdx.x) * 4;
    float4 v = *(const float4*)(W + i);
    v.x = to_tf32(v.x); v.y = to_tf32(v.y); v.z = to_tf32(v.z); v.w = to_tf32(v.w);
    *(float4*)(R + i) = v;
}

// ---------------- router ----------------
__global__ void router_kernel(const float* __restrict__ x,
                              const float* __restrict__ gw,
                              int* __restrict__ expid,
                              float* __restrict__ wt) {
    int warp = threadIdx.x >> 5, lane = threadIdx.x & 31;
    int t = blockIdx.x * 8 + warp;
    if (t >= N_TOK) return;
    const float* xr = x + (size_t)t * DIM;
    float acc[8] = {0.f,0.f,0.f,0.f,0.f,0.f,0.f,0.f};
    for (int d = lane; d < DIM; d += 32) {
        float xv = xr[d];
        const float4* g4 = (const float4*)(gw + (size_t)d * NEXP);
        float4 a = g4[0], b = g4[1];
        acc[0] += xv * a.x; acc[1] += xv * a.y; acc[2] += xv * a.z; acc[3] += xv * a.w;
        acc[4] += xv * b.x; acc[5] += xv * b.y; acc[6] += xv * b.z; acc[7] += xv * b.w;
    }
#pragma unroll
    for (int e = 0; e < 8; e++)
#pragma unroll
        for (int o = 16; o; o >>= 1) acc[e] += __shfl_xor_sync(0xffffffffu, acc[e], o);
    if (lane == 0) {
        int i0 = 0; float l0 = acc[0];
#pragma unroll
        for (int e = 1; e < 8; e++) if (acc[e] > l0) { l0 = acc[e]; i0 = e; }
        int i1 = -1; float l1 = -INFINITY;
#pragma unroll
        for (int e = 0; e < 8; e++) if (e != i0 && acc[e] > l1) { l1 = acc[e]; i1 = e; }
        float z  = expf(l1 - l0);
        float p0 = 1.0f / (1.0f + z);
        expid[t]         = i0;
        expid[N_TOK + t] = i1;
        wt[t]            = p0;
        wt[N_TOK + t]    = z * p0;
    }
}

// ---------------- deterministic slot assignment ----------------
__global__ void assign_kernel(const int* __restrict__ expid, int* __restrict__ slot) {
    __shared__ int counters[NEXP];
    __shared__ int warp_hist[8][NEXP];
    int tid = threadIdx.x, lane = tid & 31, warp = tid >> 5;
    if (tid < NEXP) counters[tid] = 0;
    __syncthreads();
    for (int a = 0; a < 2 * N_TOK; a += 256) {
        int idx = a + tid;
        int e = expid[idx];
        unsigned peers = __match_any_sync(0xffffffffu, e);
        int rank = __popc(peers & ((1u << lane) - 1u));
        if (tid < 64) ((int*)warp_hist)[tid] = 0;
        __syncthreads();
        if (rank == 0) warp_hist[warp][e] = __popc(peers);
        __syncthreads();
        int base = counters[e];
#pragma unroll
        for (int w = 0; w < 8; w++) if (w < warp) base += warp_hist[w][e];
        int s = base + rank;
        slot[idx] = (s < CAP) ? s : -1;
        __syncthreads();
        if (tid < NEXP) {
            int c = counters[tid];
#pragma unroll
            for (int w = 0; w < 8; w++) c += warp_hist[w][tid];
            counters[tid] = c;
        }
        __syncthreads();
    }
}

// ---------------- gather (writes tf32-rounded) ----------------
__global__ void gather_kernel(const float* __restrict__ x,
                              const int* __restrict__ expid,
                              const int* __restrict__ slot,
                              float* __restrict__ xbuf) {
    int a = blockIdx.x;
    int s = slot[a];
    if (s < 0) return;
    int e = expid[a];
    int t = a & (N_TOK - 1);
    const float4* src = (const float4*)(x + (size_t)t * DIM);
    float4* dst = (float4*)(xbuf + ((size_t)e * CAP + s) * DIM);
    float4 v = src[threadIdx.x];
    v.x = to_tf32(v.x); v.y = to_tf32(v.y); v.z = to_tf32(v.z); v.w = to_tf32(v.w);
    dst[threadIdx.x] = v;
}

// ============ tf32 mma.sync GEMM, all-cp.async 4-stage pipeline ============
// A: [M,K] row-major, tf32-rounded in gmem. B: [K,N] row-major, tf32-rounded in gmem.
// Block tile 128x128, ktile 16, 8 warps of 64x32 (m16n8k8).
// Smem: A [128][20] x4 stages, B [16][136] x4 stages. All compile-time stage offsets.
#define A_STAGE_W 2560   // 128*20 words
#define B_STAGE_W 2176   // 16*136 words
#define SMEM_W    (4 * (A_STAGE_W + B_STAGE_W))   // 18944 words = 75776 B

template <bool GELU>
__global__ void __launch_bounds__(256, 2)
gemm_cp(const float* __restrict__ A, const float* __restrict__ B,
        const float* __restrict__ bias, float* __restrict__ C,
        int K, int ldb, int ldc,
        long long sA, long long sB, long long sC, int sBias, int NK) {
    extern __shared__ __align__(16) float smemF[];
    const uint32_t sbase = smem_to_u32(smemF);

    const int e = blockIdx.z;
    A    += (size_t)e * sA;
    B    += (size_t)e * sB;
    C    += (size_t)e * sC;
    bias += (size_t)e * sBias;
    const int m0 = blockIdx.y * 128, n0 = blockIdx.x * 128;

    const int tid = threadIdx.x, lane = tid & 31, wid = tid >> 5;
    const int wm = (wid & 1) * 64;
    const int wn = (wid >> 1) * 32;
    const int grp = lane >> 2, qd = lane & 3;

    // A cp.async: row = tid>>2 (0..63, +64), 16B chunk = tid&3
    const int rowA = tid >> 2, chA = tid & 3;
    const float* srcA = A + (size_t)(m0 + rowA) * K + chA * 4;
    const uint32_t dstA = sbase + (uint32_t)(rowA * 80 + chA * 16);

    // B cp.async: k = tid>>5 (0..7, +8), 16B chunk = tid&31
    const int kB = tid >> 5, nB = (tid & 31) * 4;
    const float* srcB = B + (size_t)kB * ldb + n0 + nB;
    const uint32_t dstB = sbase + (uint32_t)(4 * A_STAGE_W * 4) + (uint32_t)(kB * 544 + nB * 4);

#define CPAB(kt, st)                                                         \
    do {                                                                     \
        uint32_t da = dstA + (uint32_t)((st) * (A_STAGE_W * 4));             \
        const float* sa = srcA + (size_t)(kt) * 16;                          \
        CP_ASYNC16(da, sa);                                                  \
        CP_ASYNC16(da + 64 * 80, sa + (size_t)64 * K);                       \
        uint32_t db = dstB + (uint32_t)((st) * (B_STAGE_W * 4));             \
        const float* sb_ = srcB + (size_t)(kt) * 16 * ldb;                   \
        CP_ASYNC16(db, sb_);                                                 \
        CP_ASYNC16(db + 8 * 544, sb_ + (size_t)8 * ldb);                     \
    } while (0)

    float acc[4][4][4];
#pragma unroll
    for (int i = 0; i < 4; i++)
#pragma unroll
        for (int j = 0; j < 4; j++)
#pragma unroll
            for (int r = 0; r < 4; r++) acc[i][j][r] = 0.f;

#define COMPUTE(st)                                                          \
    do {                                                                     \
        const float* aS = smemF + (st) * A_STAGE_W;                          \
        const float* bS = smemF + 4 * A_STAGE_W + (st) * B_STAGE_W;          \
        _Pragma("unroll") for (int ks = 0; ks < 2; ks++) {                   \
            const int kb = ks * 8;                                           \
            float a[4][4], b[4][2];                                          \
            _Pragma("unroll") for (int mt = 0; mt < 4; mt++) {               \
                const float* ap = aS + (wm + mt * 16 + grp) * 20 + kb + qd;  \
                a[mt][0] = ap[0];                                            \
                a[mt][1] = ap[160];                                          \
                a[mt][2] = ap[4];                                            \
                a[mt][3] = ap[164];                                          \
            }                                                                \
            _Pragma("unroll") for (int nt = 0; nt < 4; nt++) {               \
                const float* bp = bS + (kb + qd) * 136 + wn + nt * 8 + grp;  \
                b[nt][0] = bp[0];                                            \
                b[nt][1] = bp[544];                                          \
            }                                                                \
            _Pragma("unroll") for (int mt = 0; mt < 4; mt++)                 \
                _Pragma("unroll") for (int nt = 0; nt < 4; nt++)             \
                    mma8(acc[mt][nt], a[mt], b[nt]);                         \
        }                                                                    \
    } while (0)

#define ITER(kt, st)                                                         \
    do {                                                                     \
        CP_WAIT2();                                                          \
        __syncthreads();                                                     \
        COMPUTE(st);                                                         \
        if ((kt) + 3 < NK) CPAB((kt) + 3, ((st) + 3) & 3);                   \
        CP_COMMIT();                                                         \
    } while (0)

    // prologue: prefetch stages 0..2
    CPAB(0, 0); CP_COMMIT();
    CPAB(1, 1); CP_COMMIT();
    CPAB(2, 2); CP_COMMIT();

    for (int kt4 = 0; kt4 < NK; kt4 += 4) {
        ITER(kt4 + 0, 0);
        ITER(kt4 + 1, 1);
        ITER(kt4 + 2, 2);
        ITER(kt4 + 3, 3);
    }
#undef CPAB
#undef COMPUTE
#undef ITER

    // ---- epilogue: bias (+ exact GELU, tf32-rounded for GEMM1 output) ----
#pragma unroll
    for (int mt = 0; mt < 4; mt++) {
#pragma unroll
        for (int nt = 0; nt < 4; nt++) {
            int col = n0 + wn + nt * 8 + qd * 2;
            float b0 = bias[col], b1 = bias[col + 1];
#pragma unroll
            for (int h = 0; h < 2; h++) {
                size_t row = (size_t)(m0 + wm + mt * 16 + grp + h * 8);
                float v0 = acc[mt][nt][h * 2 + 0] + b0;
                float v1 = acc[mt][nt][h * 2 + 1] + b1;
                if (GELU) {
                    v0 = to_tf32(0.5f * v0 * (1.0f + erff(v0 * 0.70710678118654752f)));
                    v1 = to_tf32(0.5f * v1 * (1.0f + erff(v1 * 0.70710678118654752f)));
                }
                *(float2*)(C + row * ldc + col) = make_float2(v0, v1);
            }
        }
    }
}

// ---------------- combine ----------------
__global__ void combine_kernel(const int* __restrict__ expid,
                               const int* __restrict__ slot,
                               const float* __restrict__ wt,
                               const float* __restrict__ eout,
                               float* __restrict__ out) {
    int t = blockIdx.x;
    int e0 = expid[t],          s0 = slot[t];          float w0 = wt[t];
    int e1 = expid[N_TOK + t],  s1 = slot[N_TOK + t];  float w1 = wt[N_TOK + t];
    int i = threadIdx.x;
    float4 r = make_float4(0.f, 0.f, 0.f, 0.f);
    if (s0 >= 0) {
        float4 v = ((const float4*)(eout + ((size_t)e0 * CAP + s0) * DIM))[i];
        r.x += w0 * v.x; r.y += w0 * v.y; r.z += w0 * v.z; r.w += w0 * v.w;
    }
    if (s1 >= 0) {
        float4 v = ((const float4*)(eout + ((size_t)e1 * CAP + s1) * DIM))[i];
        r.x += w1 * v.x; r.y += w1 * v.y; r.z += w1 * v.z; r.w += w1 * v.w;
    }
    ((float4*)(out + (size_t)t * DIM))[i] = r;
}

// ---------------- launch ----------------
extern "C" void kernel_launch(void* const* d_in, const int* in_sizes, int n_in,
                              void* d_out, int out_size) {
    const float* x         = (const float*)d_in[0];
    const float* gate_w    = (const float*)d_in[1];
    const float* c_fc      = (const float*)d_in[2];
    const float* fc_bias   = (const float*)d_in[3];
    const float* c_proj    = (const float*)d_in[4];
    const float* proj_bias = (const float*)d_in[5];
    float* out = (float*)d_out;

    float *xbuf, *hbuf, *eout, *wt, *wr1, *wr2;
    int *expid, *slot;
    cudaGetSymbolAddress((void**)&xbuf,  g_xbuf);
    cudaGetSymbolAddress((void**)&hbuf,  g_h);
    cudaGetSymbolAddress((void**)&eout,  g_eout);
    cudaGetSymbolAddress((void**)&wr1,   g_wr1);
    cudaGetSymbolAddress((void**)&wr2,   g_wr2);
    cudaGetSymbolAddress((void**)&expid, g_expid);
    cudaGetSymbolAddress((void**)&slot,  g_slot);
    cudaGetSymbolAddress((void**)&wt,    g_wtp);

    const int smem_bytes = SMEM_W * 4;
    cudaFuncSetAttribute(gemm_cp<true>,  cudaFuncAttributeMaxDynamicSharedMemorySize, smem_bytes);
    cudaFuncSetAttribute(gemm_cp<false>, cudaFuncAttributeMaxDynamicSharedMemorySize, smem_bytes);

    router_kernel<<<N_TOK / 8, 256>>>(x, gate_w, expid, wt);
    assign_kernel<<<1, 256>>>(expid, slot);
    gather_kernel<<<2 * N_TOK, 256>>>(x, expid, slot, xbuf);

    // pre-round weights to tf32 (element count = NEXP*DIM*HID for each)
    const size_t wn = (size_t)NEXP * DIM * HID;
    round_kernel<<<(unsigned)(wn / 1024), 256>>>(c_fc,   wr1);
    round_kernel<<<(unsigned)(wn / 1024), 256>>>(c_proj, wr2);

    // GEMM1 + GELU: [CAP,DIM] x [DIM,HID] -> [CAP,HID]
    dim3 g1(HID / 128, CAP / 128, NEXP);
    gemm_cp<true><<<g1, 256, smem_bytes>>>(xbuf, wr1, fc_bias, hbuf,
                                           DIM, HID, HID,
                                           (long long)CAP * DIM, (long long)DIM * HID,
                                           (long long)CAP * HID, HID, DIM / 16);

    // GEMM2 + bias: [CAP,HID] x [HID,DIM] -> [CAP,DIM]
    dim3 g2(DIM / 128, CAP / 128, NEXP);
    gemm_cp<false><<<g2, 256, smem_bytes>>>(hbuf, wr2, proj_bias, eout,
                                            HID, DIM, DIM,
                                            (long long)CAP * HID, (long long)HID * DIM,
                                            (long long)CAP * DIM, DIM, HID / 16);

    combine_kernel<<<N_TOK, 256>>>(expid, slot, wt, eout, out);
}

// round 6
// speedup vs baseline: 4.2172x; 1.1468x over previous
#include <cuda_runtime.h>
#include <math.h>
#include <stdint.h>

#define N_TOK 4096
#define DIM   1024
#define HID   4096
#define NEXP  8
#define CAP   1280   // int(1.25 * 4096 * 2 / 8)

// ---------------- scratch (static device globals; no allocation) ----------------
// xbuf/hbuf live in "A-fragment-major" layout:
//   A'[(m>>4) * (K/8) + (k>>3)][lane][v], 128 floats per 16x8 block,
//   lane = (r&7)*4 + (kk&3), v = (r>>3) + 2*(kk>>2),  r=m&15, kk=k&7.
__device__ float g_xbuf[(size_t)NEXP * CAP * DIM];   // gathered inputs (tf32, A'-layout)
__device__ float g_h   [(size_t)NEXP * CAP * HID];   // hidden after gelu (tf32, A'-layout)
__device__ float g_eout[(size_t)NEXP * CAP * DIM];   // expert outputs (fp32, row-major)
__device__ float g_wr1 [(size_t)NEXP * DIM * HID];   // c_fc   tf32-rounded, row-major [K,N]
__device__ float g_wr2 [(size_t)NEXP * HID * DIM];   // c_proj tf32-rounded, row-major [K,N]
__device__ int   g_expid[2 * N_TOK];
__device__ int   g_slot [2 * N_TOK];
__device__ float g_wtp  [2 * N_TOK];

__device__ __forceinline__ float to_tf32(float x) {
    float r; asm("cvt.rna.tf32.f32 %0, %1;" : "=f"(r) : "f"(x)); return r;
}
__device__ __forceinline__ uint32_t smem_to_u32(const void* p) {
    uint32_t a;
    asm("{ .reg .u64 t; cvta.to.shared.u64 t, %1; cvt.u32.u64 %0, t; }" : "=r"(a) : "l"(p));
    return a;
}
#define CP_ASYNC16(dst, src) \
    asm volatile("cp.async.cg.shared.global [%0], [%1], 16;\n" :: "r"(dst), "l"(src))
#define CP_COMMIT() asm volatile("cp.async.commit_group;\n" ::: "memory")
#define CP_WAIT2()  asm volatile("cp.async.wait_group 2;\n" ::: "memory")

__device__ __forceinline__ void mma8(float d[4], const float* a, const float b[2]) {
    const uint32_t* A = (const uint32_t*)a;
    const uint32_t* B = (const uint32_t*)b;
    asm volatile(
        "mma.sync.aligned.m16n8k8.row.col.f32.tf32.tf32.f32 "
        "{%0,%1,%2,%3},{%4,%5,%6,%7},{%8,%9},{%0,%1,%2,%3};"
        : "+f"(d[0]), "+f"(d[1]), "+f"(d[2]), "+f"(d[3])
        : "r"(A[0]), "r"(A[1]), "r"(A[2]), "r"(A[3]), "r"(B[0]), "r"(B[1]));
}

// ---------------- elementwise tf32 rounding of weights ----------------
__global__ void round_kernel(const float* __restrict__ W, float* __restrict__ R) {
    size_t i = ((size_t)blockIdx.x * 256 + threadIdx.x) * 4;
    float4 v = *(const float4*)(W + i);
    v.x = to_tf32(v.x); v.y = to_tf32(v.y); v.z = to_tf32(v.z); v.w = to_tf32(v.w);
    *(float4*)(R + i) = v;
}

// ---------------- router ----------------
__global__ void router_kernel(const float* __restrict__ x,
                              const float* __restrict__ gw,
                              int* __restrict__ expid,
                              float* __restrict__ wt) {
    int warp = threadIdx.x >> 5, lane = threadIdx.x & 31;
    int t = blockIdx.x * 8 + warp;
    if (t >= N_TOK) return;
    const float* xr = x + (size_t)t * DIM;
    float acc[8] = {0.f,0.f,0.f,0.f,0.f,0.f,0.f,0.f};
    for (int d = lane; d < DIM; d += 32) {
        float xv = xr[d];
        const float4* g4 = (const float4*)(gw + (size_t)d * NEXP);
        float4 a = g4[0], b = g4[1];
        acc[0] += xv * a.x; acc[1] += xv * a.y; acc[2] += xv * a.z; acc[3] += xv * a.w;
        acc[4] += xv * b.x; acc[5] += xv * b.y; acc[6] += xv * b.z; acc[7] += xv * b.w;
    }
#pragma unroll
    for (int e = 0; e < 8; e++)
#pragma unroll
        for (int o = 16; o; o >>= 1) acc[e] += __shfl_xor_sync(0xffffffffu, acc[e], o);
    if (lane == 0) {
        int i0 = 0; float l0 = acc[0];
#pragma unroll
        for (int e = 1; e < 8; e++) if (acc[e] > l0) { l0 = acc[e]; i0 = e; }
        int i1 = -1; float l1 = -INFINITY;
#pragma unroll
        for (int e = 0; e < 8; e++) if (e != i0 && acc[e] > l1) { l1 = acc[e]; i1 = e; }
        float z  = expf(l1 - l0);
        float p0 = 1.0f / (1.0f + z);
        expid[t]         = i0;
        expid[N_TOK + t] = i1;
        wt[t]            = p0;
        wt[N_TOK + t]    = z * p0;
    }
}

// ---------------- deterministic slot assignment ----------------
__global__ void assign_kernel(const int* __restrict__ expid, int* __restrict__ slot) {
    __shared__ int counters[NEXP];
    __shared__ int warp_hist[8][NEXP];
    int tid = threadIdx.x, lane = tid & 31, warp = tid >> 5;
    if (tid < NEXP) counters[tid] = 0;
    __syncthreads();
    for (int a = 0; a < 2 * N_TOK; a += 256) {
        int idx = a + tid;
        int e = expid[idx];
        unsigned peers = __match_any_sync(0xffffffffu, e);
        int rank = __popc(peers & ((1u << lane) - 1u));
        if (tid < 64) ((int*)warp_hist)[tid] = 0;
        __syncthreads();
        if (rank == 0) warp_hist[warp][e] = __popc(peers);
        __syncthreads();
        int base = counters[e];
#pragma unroll
        for (int w = 0; w < 8; w++) if (w < warp) base += warp_hist[w][e];
        int s = base + rank;
        slot[idx] = (s < CAP) ? s : -1;
        __syncthreads();
        if (tid < NEXP) {
            int c = counters[tid];
#pragma unroll
            for (int w = 0; w < 8; w++) c += warp_hist[w][tid];
            counters[tid] = c;
        }
        __syncthreads();
    }
}

// ---------------- gather: x row -> expert buffer in A'-layout (tf32-rounded) ----------------
__global__ void gather_kernel(const float* __restrict__ x,
                              const int* __restrict__ expid,
                              const int* __restrict__ slot,
                              float* __restrict__ xbuf) {
    int a = blockIdx.x;
    int s = slot[a];
    if (s < 0) return;
    int e = expid[a];
    int t = a & (N_TOK - 1);
    int tid = threadIdx.x;
    float4 v = ((const float4*)(x + (size_t)t * DIM))[tid];
    // k = tid*4 .. tid*4+3 :  k8 = tid>>1,  kk>>2 = tid&1,  kk&3 = 0..3
    int r = s & 15;
    float* base = xbuf + (size_t)e * CAP * DIM
                + ((size_t)(s >> 4) * (DIM >> 3) + (tid >> 1)) * 128
                + ((r & 7) * 4) * 4 + (r >> 3) + 2 * (tid & 1);
    base[0]  = to_tf32(v.x);
    base[4]  = to_tf32(v.y);
    base[8]  = to_tf32(v.z);
    base[12] = to_tf32(v.w);
}

// ============ tf32 mma.sync GEMM, all-cp.async 4-stage, fragment-major A ============
// A: A'-layout (tf32 in gmem). B: [K,N] row-major tf32 in gmem.
// Block tile 128x128, ktile 16, 8 warps of 64x32 (m16n8k8).
// Smem: A stage = 16 blocks x 512B = 8192B (frag-major, LDS.128 conflict-free),
//       B stage = [16][136] floats = 8704B (scalar LDS bank 8*qd+grp, conflict-free).
#define A_STAGE_W 2048
#define B_STAGE_W 2176
#define SMEM_W    (4 * (A_STAGE_W + B_STAGE_W))   // 16896 words = 67584 B

// AOUT: if true, write C in A'-layout (for next GEMM's A) + exact GELU + tf32 round.
template <bool AOUT>
__global__ void __launch_bounds__(256, 2)
gemm_cp(const float* __restrict__ A, const float* __restrict__ B,
        const float* __restrict__ bias, float* __restrict__ C,
        int K, int ldb, int ldc,
        long long sA, long long sB, long long sC, int sBias, int NK) {
    extern __shared__ __align__(16) float smemF[];
    const uint32_t sbase = smem_to_u32(smemF);

    const int e = blockIdx.z;
    A    += (size_t)e * sA;
    B    += (size_t)e * sB;
    C    += (size_t)e * sC;
    bias += (size_t)e * sBias;
    const int m0 = blockIdx.y * 128, n0 = blockIdx.x * 128;

    const int tid = threadIdx.x, lane = tid & 31, wid = tid >> 5;
    const int wm16 = (wid & 1) * 4;       // m16-block offset within CTA tile
    const int wn = (wid >> 1) * 32;
    const int grp = lane >> 2, qd = lane & 3;

    // A cp.async: blkT = m16 block (0..7), laneT picks the 16B fragment
    const int laneT = tid & 31, blkT = tid >> 5;
    const float* srcA = A + ((size_t)((m0 >> 4) + blkT) * (K >> 3)) * 128 + laneT * 4;
    const uint32_t dstA = sbase + (uint32_t)(blkT * 512 + laneT * 16);

    // B cp.async: k = tid>>5 (0..7, +8), 16B chunk = tid&31
    const int kB = tid >> 5, nB = (tid & 31) * 4;
    const float* srcB = B + (size_t)kB * ldb + n0 + nB;
    const uint32_t dstB = sbase + (uint32_t)(4 * A_STAGE_W * 4) + (uint32_t)(kB * 544 + nB * 4);

#define CPAB(kt, st)                                                         \
    do {                                                                     \
        uint32_t da = dstA + (uint32_t)((st) * (A_STAGE_W * 4));             \
        const float* sa = srcA + (size_t)(2 * (kt)) * 128;                   \
        CP_ASYNC16(da, sa);                  /* ks=0 block */                \
        CP_ASYNC16(da + 4096, sa + 128);     /* ks=1 block */                \
        uint32_t db = dstB + (uint32_t)((st) * (B_STAGE_W * 4));             \
        const float* sb_ = srcB + (size_t)(kt) * 16 * ldb;                   \
        CP_ASYNC16(db, sb_);                                                 \
        CP_ASYNC16(db + 8 * 544, sb_ + (size_t)8 * ldb);                     \
    } while (0)

    float acc[4][4][4];
#pragma unroll
    for (int i = 0; i < 4; i++)
#pragma unroll
        for (int j = 0; j < 4; j++)
#pragma unroll
            for (int r = 0; r < 4; r++) acc[i][j][r] = 0.f;

#define COMPUTE(st)                                                          \
    do {                                                                     \
        const float* aS = smemF + (st) * A_STAGE_W;                          \
        const float* bS = smemF + 4 * A_STAGE_W + (st) * B_STAGE_W;          \
        _Pragma("unroll") for (int ks = 0; ks < 2; ks++) {                   \
            float4 a[4]; float b[4][2];                                      \
            _Pragma("unroll") for (int mt = 0; mt < 4; mt++)                 \
                a[mt] = *(const float4*)(aS + (ks * 8 + wm16 + mt) * 128 +   \
                                         lane * 4);                          \
            _Pragma("unroll") for (int nt = 0; nt < 4; nt++) {               \
                const float* bp = bS + (ks * 8 + qd) * 136 + wn + nt * 8 + grp; \
                b[nt][0] = bp[0];                                            \
                b[nt][1] = bp[544];                                          \
            }                                                                \
            _Pragma("unroll") for (int mt = 0; mt < 4; mt++)                 \
                _Pragma("unroll") for (int nt = 0; nt < 4; nt++)             \
                    mma8(acc[mt][nt], (const float*)&a[mt], b[nt]);          \
        }                                                                    \
    } while (0)

#define ITER(kt, st)                                                         \
    do {                                                                     \
        CP_WAIT2();                                                          \
        __syncthreads();                                                     \
        COMPUTE(st);                                                         \
        if ((kt) + 3 < NK) CPAB((kt) + 3, ((st) + 3) & 3);                   \
        CP_COMMIT();                                                         \
    } while (0)

    // prologue: prefetch stages 0..2
    CPAB(0, 0); CP_COMMIT();
    CPAB(1, 1); CP_COMMIT();
    CPAB(2, 2); CP_COMMIT();

    for (int kt4 = 0; kt4 < NK; kt4 += 4) {
        ITER(kt4 + 0, 0);
        ITER(kt4 + 1, 1);
        ITER(kt4 + 2, 2);
        ITER(kt4 + 3, 3);
    }
#undef CPAB
#undef COMPUTE
#undef ITER

    // ---- epilogue ----
#pragma unroll
    for (int mt = 0; mt < 4; mt++) {
#pragma unroll
        for (int nt = 0; nt < 4; nt++) {
            int col = n0 + wn + nt * 8 + qd * 2;
            float b0 = bias[col], b1 = bias[col + 1];
#pragma unroll
            for (int h = 0; h < 2; h++) {
                float v0 = acc[mt][nt][h * 2 + 0] + b0;
                float v1 = acc[mt][nt][h * 2 + 1] + b1;
                if (AOUT) {
                    // exact GELU + tf32 round, store into A'-layout for next GEMM
                    v0 = to_tf32(0.5f * v0 * (1.0f + erff(v0 * 0.70710678118654752f)));
                    v1 = to_tf32(0.5f * v1 * (1.0f + erff(v1 * 0.70710678118654752f)));
                    size_t row16 = (size_t)((m0 >> 4) + wm16 + mt);
                    int colblk = ((n0 + wn) >> 3) + nt;
                    float* cw = C + (row16 * (ldc >> 3) + colblk) * 128
                              + (grp * 4 + ((2 * qd) & 3)) * 4 + h + 2 * (qd >> 1);
                    cw[0] = v0;
                    cw[4] = v1;
                } else {
                    size_t row = (size_t)(m0 + (wm16 << 4) + mt * 16 + grp + h * 8);
                    *(float2*)(C + row * ldc + col) = make_float2(v0, v1);
                }
            }
        }
    }
}

// ---------------- combine ----------------
__global__ void combine_kernel(const int* __restrict__ expid,
                               const int* __restrict__ slot,
                               const float* __restrict__ wt,
                               const float* __restrict__ eout,
                               float* __restrict__ out) {
    int t = blockIdx.x;
    int e0 = expid[t],          s0 = slot[t];          float w0 = wt[t];
    int e1 = expid[N_TOK + t],  s1 = slot[N_TOK + t];  float w1 = wt[N_TOK + t];
    int i = threadIdx.x;
    float4 r = make_float4(0.f, 0.f, 0.f, 0.f);
    if (s0 >= 0) {
        float4 v = ((const float4*)(eout + ((size_t)e0 * CAP + s0) * DIM))[i];
        r.x += w0 * v.x; r.y += w0 * v.y; r.z += w0 * v.z; r.w += w0 * v.w;
    }
    if (s1 >= 0) {
        float4 v = ((const float4*)(eout + ((size_t)e1 * CAP + s1) * DIM))[i];
        r.x += w1 * v.x; r.y += w1 * v.y; r.z += w1 * v.z; r.w += w1 * v.w;
    }
    ((float4*)(out + (size_t)t * DIM))[i] = r;
}

// ---------------- launch ----------------
extern "C" void kernel_launch(void* const* d_in, const int* in_sizes, int n_in,
                              void* d_out, int out_size) {
    const float* x         = (const float*)d_in[0];
    const float* gate_w    = (const float*)d_in[1];
    const float* c_fc      = (const float*)d_in[2];
    const float* fc_bias   = (const float*)d_in[3];
    const float* c_proj    = (const float*)d_in[4];
    const float* proj_bias = (const float*)d_in[5];
    float* out = (float*)d_out;

    float *xbuf, *hbuf, *eout, *wt, *wr1, *wr2;
    int *expid, *slot;
    cudaGetSymbolAddress((void**)&xbuf,  g_xbuf);
    cudaGetSymbolAddress((void**)&hbuf,  g_h);
    cudaGetSymbolAddress((void**)&eout,  g_eout);
    cudaGetSymbolAddress((void**)&wr1,   g_wr1);
    cudaGetSymbolAddress((void**)&wr2,   g_wr2);
    cudaGetSymbolAddress((void**)&expid, g_expid);
    cudaGetSymbolAddress((void**)&slot,  g_slot);
    cudaGetSymbolAddress((void**)&wt,    g_wtp);

    const int smem_bytes = SMEM_W * 4;
    cudaFuncSetAttribute(gemm_cp<true>,  cudaFuncAttributeMaxDynamicSharedMemorySize, smem_bytes);
    cudaFuncSetAttribute(gemm_cp<false>, cudaFuncAttributeMaxDynamicSharedMemorySize, smem_bytes);

    router_kernel<<<N_TOK / 8, 256>>>(x, gate_w, expid, wt);
    assign_kernel<<<1, 256>>>(expid, slot);
    gather_kernel<<<2 * N_TOK, 256>>>(x, expid, slot, xbuf);

    // pre-round weights to tf32
    const size_t wn = (size_t)NEXP * DIM * HID;
    round_kernel<<<(unsigned)(wn / 1024), 256>>>(c_fc,   wr1);
    round_kernel<<<(unsigned)(wn / 1024), 256>>>(c_proj, wr2);

    // GEMM1 + GELU: [CAP,DIM] x [DIM,HID] -> [CAP,HID]  (output in A'-layout)
    dim3 g1(HID / 128, CAP / 128, NEXP);
    gemm_cp<true><<<g1, 256, smem_bytes>>>(xbuf, wr1, fc_bias, hbuf,
                                           DIM, HID, HID,
                                           (long long)CAP * DIM, (long long)DIM * HID,
                                           (long long)CAP * HID, HID, DIM / 16);

    // GEMM2 + bias: [CAP,HID] x [HID,DIM] -> [CAP,DIM]  (row-major output)
    dim3 g2(DIM / 128, CAP / 128, NEXP);
    gemm_cp<false><<<g2, 256, smem_bytes>>>(hbuf, wr2, proj_bias, eout,
                                            HID, DIM, DIM,
                                            (long long)CAP * HID, (long long)HID * DIM,
                                            (long long)CAP * DIM, DIM, HID / 16);

    combine_kernel<<<N_TOK, 256>>>(expid, slot, wt, eout, out);
}

// round 7
// speedup vs baseline: 4.2708x; 1.0127x over previous
#include <cuda_runtime.h>
#include <math.h>
#include <stdint.h>

#define N_TOK 4096
#define DIM   1024
#define HID   4096
#define NEXP  8
#define CAP   1280   // int(1.25 * 4096 * 2 / 8)

// ---------------- scratch (static device globals; no allocation) ----------------
// xbuf/hbuf: "A-fragment-major": A'[(m>>4)*(K/8) + (k>>3)][128],
//   float idx = lane*4 + v, lane=(m&7)*4+(k&3), v=((m>>3)&1)+2*((k>>2)&1).
// wr1/wr2: "B-fragment-major": B'[(n>>3)*(K/16) + (k>>4)][128],
//   float idx = lane*4 + v, lane=(n&7)*4+(k&3), v=((k>>2)&1)+2*((k>>3)&1).
__device__ float g_xbuf[(size_t)NEXP * CAP * DIM];
__device__ float g_h   [(size_t)NEXP * CAP * HID];
__device__ float g_eout[(size_t)NEXP * CAP * DIM];
__device__ float g_wr1 [(size_t)NEXP * DIM * HID];
__device__ float g_wr2 [(size_t)NEXP * HID * DIM];
__device__ int   g_expid[2 * N_TOK];
__device__ int   g_slot [2 * N_TOK];
__device__ float g_wtp  [2 * N_TOK];

__device__ __forceinline__ float to_tf32(float x) {
    float r; asm("cvt.rna.tf32.f32 %0, %1;" : "=f"(r) : "f"(x)); return r;
}
__device__ __forceinline__ uint32_t smem_to_u32(const void* p) {
    uint32_t a;
    asm("{ .reg .u64 t; cvta.to.shared.u64 t, %1; cvt.u32.u64 %0, t; }" : "=r"(a) : "l"(p));
    return a;
}
#define CP_ASYNC16(dst, src) \
    asm volatile("cp.async.cg.shared.global [%0], [%1], 16;\n" :: "r"(dst), "l"(src))
#define CP_COMMIT() asm volatile("cp.async.commit_group;\n" ::: "memory")
#define CP_WAIT2()  asm volatile("cp.async.wait_group 2;\n" ::: "memory")

__device__ __forceinline__ void mma8(float d[4], const float* a, const float* b) {
    const uint32_t* A = (const uint32_t*)a;
    const uint32_t* B = (const uint32_t*)b;
    asm volatile(
        "mma.sync.aligned.m16n8k8.row.col.f32.tf32.tf32.f32 "
        "{%0,%1,%2,%3},{%4,%5,%6,%7},{%8,%9},{%0,%1,%2,%3};"
        : "+f"(d[0]), "+f"(d[1]), "+f"(d[2]), "+f"(d[3])
        : "r"(A[0]), "r"(A[1]), "r"(A[2]), "r"(A[3]), "r"(B[0]), "r"(B[1]));
}

// ---------------- weight permute+round: W[K,N] row-major -> B'-fragment layout ----------------
// one warp per 16x8 (k x n) output block (512B), 8 warps per CTA
__global__ void permute_b_kernel(const float* __restrict__ W, float* __restrict__ R,
                                 int K, int N) {
    int gw   = (blockIdx.x * 256 + threadIdx.x) >> 5;
    int lane = threadIdx.x & 31;
    int bpe  = (N >> 3) * (K >> 4);
    int e    = gw / bpe;
    int b    = gw - e * bpe;
    int n8   = b / (K >> 4);
    int k16  = b - n8 * (K >> 4);
    const float* We = W + (size_t)e * K * N;
    int grp = lane >> 2, qd = lane & 3;
    const float* p = We + (size_t)(k16 * 16 + qd) * N + n8 * 8 + grp;
    float4 v;
    v.x = to_tf32(p[0]);
    v.y = to_tf32(p[(size_t)4 * N]);
    v.z = to_tf32(p[(size_t)8 * N]);
    v.w = to_tf32(p[(size_t)12 * N]);
    *(float4*)(R + ((size_t)e * bpe + b) * 128 + lane * 4) = v;
}

// ---------------- router ----------------
__global__ void router_kernel(const float* __restrict__ x,
                              const float* __restrict__ gw,
                              int* __restrict__ expid,
                              float* __restrict__ wt) {
    int warp = threadIdx.x >> 5, lane = threadIdx.x & 31;
    int t = blockIdx.x * 8 + warp;
    if (t >= N_TOK) return;
    const float* xr = x + (size_t)t * DIM;
    float acc[8] = {0.f,0.f,0.f,0.f,0.f,0.f,0.f,0.f};
    for (int d = lane; d < DIM; d += 32) {
        float xv = xr[d];
        const float4* g4 = (const float4*)(gw + (size_t)d * NEXP);
        float4 a = g4[0], b = g4[1];
        acc[0] += xv * a.x; acc[1] += xv * a.y; acc[2] += xv * a.z; acc[3] += xv * a.w;
        acc[4] += xv * b.x; acc[5] += xv * b.y; acc[6] += xv * b.z; acc[7] += xv * b.w;
    }
#pragma unroll
    for (int e = 0; e < 8; e++)
#pragma unroll
        for (int o = 16; o; o >>= 1) acc[e] += __shfl_xor_sync(0xffffffffu, acc[e], o);
    if (lane == 0) {
        int i0 = 0; float l0 = acc[0];
#pragma unroll
        for (int e = 1; e < 8; e++) if (acc[e] > l0) { l0 = acc[e]; i0 = e; }
        int i1 = -1; float l1 = -INFINITY;
#pragma unroll
        for (int e = 0; e < 8; e++) if (e != i0 && acc[e] > l1) { l1 = acc[e]; i1 = e; }
        float z  = expf(l1 - l0);
        float p0 = 1.0f / (1.0f + z);
        expid[t]         = i0;
        expid[N_TOK + t] = i1;
        wt[t]            = p0;
        wt[N_TOK + t]    = z * p0;
    }
}

// ---------------- deterministic slot assignment ----------------
__global__ void assign_kernel(const int* __restrict__ expid, int* __restrict__ slot) {
    __shared__ int counters[NEXP];
    __shared__ int warp_hist[8][NEXP];
    int tid = threadIdx.x, lane = tid & 31, warp = tid >> 5;
    if (tid < NEXP) counters[tid] = 0;
    __syncthreads();
    for (int a = 0; a < 2 * N_TOK; a += 256) {
        int idx = a + tid;
        int e = expid[idx];
        unsigned peers = __match_any_sync(0xffffffffu, e);
        int rank = __popc(peers & ((1u << lane) - 1u));
        if (tid < 64) ((int*)warp_hist)[tid] = 0;
        __syncthreads();
        if (rank == 0) warp_hist[warp][e] = __popc(peers);
        __syncthreads();
        int base = counters[e];
#pragma unroll
        for (int w = 0; w < 8; w++) if (w < warp) base += warp_hist[w][e];
        int s = base + rank;
        slot[idx] = (s < CAP) ? s : -1;
        __syncthreads();
        if (tid < NEXP) {
            int c = counters[tid];
#pragma unroll
            for (int w = 0; w < 8; w++) c += warp_hist[w][tid];
            counters[tid] = c;
        }
        __syncthreads();
    }
}

// ---------------- gather: x row -> expert buffer in A'-layout (tf32-rounded) ----------------
__global__ void gather_kernel(const float* __restrict__ x,
                              const int* __restrict__ expid,
                              const int* __restrict__ slot,
                              float* __restrict__ xbuf) {
    int a = blockIdx.x;
    int s = slot[a];
    if (s < 0) return;
    int e = expid[a];
    int t = a & (N_TOK - 1);
    int tid = threadIdx.x;
    float4 v = ((const float4*)(x + (size_t)t * DIM))[tid];
    int r = s & 15;
    float* base = xbuf + (size_t)e * CAP * DIM
                + ((size_t)(s >> 4) * (DIM >> 3) + (tid >> 1)) * 128
                + ((r & 7) * 4) * 4 + (r >> 3) + 2 * (tid & 1);
    base[0]  = to_tf32(v.x);
    base[4]  = to_tf32(v.y);
    base[8]  = to_tf32(v.z);
    base[12] = to_tf32(v.w);
}

// ============ tf32 mma.sync GEMM: fragment-major A and B, all-cp.async 4-stage ============
// Block tile 128x128, ktile 16, 8 warps of 64x32 (m16n8k8).
// Smem per stage: A = 16 blocks x 512B = 8192B, B = 16 blocks x 512B = 8192B.
#define A_STAGE_W 2048
#define B_STAGE_W 2048
#define SMEM_W    (4 * (A_STAGE_W + B_STAGE_W))   // 16384 words = 65536 B

// AOUT: if true, write C in A'-layout (for next GEMM's A) + exact GELU + tf32 round.
template <bool AOUT>
__global__ void __launch_bounds__(256, 2)
gemm_cp(const float* __restrict__ A, const float* __restrict__ B,
        const float* __restrict__ bias, float* __restrict__ C,
        int K, int ldc,
        long long sA, long long sB, long long sC, int sBias, int NK) {
    extern __shared__ __align__(16) float smemF[];
    const uint32_t sbase = smem_to_u32(smemF);

    const int e = blockIdx.z;
    A    += (size_t)e * sA;
    B    += (size_t)e * sB;
    C    += (size_t)e * sC;
    bias += (size_t)e * sBias;
    const int m0 = blockIdx.y * 128, n0 = blockIdx.x * 128;

    const int tid = threadIdx.x, lane = tid & 31, wid = tid >> 5;
    const int wm16 = (wid & 1) * 4;       // m16-block offset within CTA tile
    const int wn = (wid >> 1) * 32;
    const int grp = lane >> 2, qd = lane & 3;

    // A cp.async: blkT = m16 block (0..7), laneT = 16B fragment within block
    const int laneT = tid & 31, blkT = tid >> 5;
    const float* srcA = A + ((size_t)((m0 >> 4) + blkT) * (K >> 3)) * 128 + laneT * 4;
    const uint32_t dstA = sbase + (uint32_t)(blkT * 512 + laneT * 16);

    // B cp.async: blkB = n8 block (0..15), fB = float4-pair within block
    const int blkB = tid >> 4, fB = (tid & 15) * 8;
    const float* srcB = B + ((size_t)((n0 >> 3) + blkB) * NK) * 128 + fB;
    const uint32_t dstB = sbase + (uint32_t)(4 * A_STAGE_W * 4) + (uint32_t)(blkB * 512 + fB * 4);

#define CPAB(kt, st)                                                         \
    do {                                                                     \
        uint32_t da = dstA + (uint32_t)((st) * (A_STAGE_W * 4));             \
        const float* sa = srcA + (size_t)(2 * (kt)) * 128;                   \
        CP_ASYNC16(da, sa);                  /* ks=0 block */                \
        CP_ASYNC16(da + 4096, sa + 128);     /* ks=1 block */                \
        uint32_t db = dstB + (uint32_t)((st) * (B_STAGE_W * 4));             \
        const float* sb_ = srcB + (size_t)(kt) * 128;                        \
        CP_ASYNC16(db, sb_);                                                 \
        CP_ASYNC16(db + 16, sb_ + 4);                                        \
    } while (0)

    float acc[4][4][4];
#pragma unroll
    for (int i = 0; i < 4; i++)
#pragma unroll
        for (int j = 0; j < 4; j++)
#pragma unroll
            for (int r = 0; r < 4; r++) acc[i][j][r] = 0.f;

#define COMPUTE(st)                                                          \
    do {                                                                     \
        const float* aS = smemF + (st) * A_STAGE_W;                          \
        const float* bS = smemF + 4 * A_STAGE_W + (st) * B_STAGE_W;          \
        float4 bv[4];                                                        \
        _Pragma("unroll") for (int nt = 0; nt < 4; nt++)                     \
            bv[nt] = *(const float4*)(bS + ((wn >> 3) + nt) * 128 + lane * 4); \
        _Pragma("unroll") for (int ks = 0; ks < 2; ks++) {                   \
            float4 a[4];                                                     \
            _Pragma("unroll") for (int mt = 0; mt < 4; mt++)                 \
                a[mt] = *(const float4*)(aS + (ks * 8 + wm16 + mt) * 128 +   \
                                         lane * 4);                          \
            _Pragma("unroll") for (int mt = 0; mt < 4; mt++)                 \
                _Pragma("unroll") for (int nt = 0; nt < 4; nt++)             \
                    mma8(acc[mt][nt], (const float*)&a[mt],                  \
                         ks ? &bv[nt].z : &bv[nt].x);                        \
        }                                                                    \
    } while (0)

#define ITER(kt, st)                                                         \
    do {                                                                     \
        CP_WAIT2();                                                          \
        __syncthreads();                                                     \
        COMPUTE(st);                                                         \
        if ((kt) + 3 < NK) CPAB((kt) + 3, ((st) + 3) & 3);                   \
        CP_COMMIT();                                                         \
    } while (0)

    // prologue: prefetch stages 0..2
    CPAB(0, 0); CP_COMMIT();
    CPAB(1, 1); CP_COMMIT();
    CPAB(2, 2); CP_COMMIT();

    for (int kt4 = 0; kt4 < NK; kt4 += 4) {
        ITER(kt4 + 0, 0);
        ITER(kt4 + 1, 1);
        ITER(kt4 + 2, 2);
        ITER(kt4 + 3, 3);
    }
#undef CPAB
#undef COMPUTE
#undef ITER

    // ---- epilogue ----
#pragma unroll
    for (int mt = 0; mt < 4; mt++) {
#pragma unroll
        for (int nt = 0; nt < 4; nt++) {
            int col = n0 + wn + nt * 8 + qd * 2;
            float b0 = bias[col], b1 = bias[col + 1];
#pragma unroll
            for (int h = 0; h < 2; h++) {
                float v0 = acc[mt][nt][h * 2 + 0] + b0;
                float v1 = acc[mt][nt][h * 2 + 1] + b1;
                if (AOUT) {
                    v0 = to_tf32(0.5f * v0 * (1.0f + erff(v0 * 0.70710678118654752f)));
                    v1 = to_tf32(0.5f * v1 * (1.0f + erff(v1 * 0.70710678118654752f)));
                    size_t row16 = (size_t)((m0 >> 4) + wm16 + mt);
                    int colblk = ((n0 + wn) >> 3) + nt;
                    float* cw = C + (row16 * (ldc >> 3) + colblk) * 128
                              + (grp * 4 + ((2 * qd) & 3)) * 4 + h + 2 * (qd >> 1);
                    cw[0] = v0;
                    cw[4] = v1;
                } else {
                    size_t row = (size_t)(m0 + (wm16 << 4) + mt * 16 + grp + h * 8);
                    *(float2*)(C + row * ldc + col) = make_float2(v0, v1);
                }
            }
        }
    }
}

// ---------------- combine ----------------
__global__ void combine_kernel(const int* __restrict__ expid,
                               const int* __restrict__ slot,
                               const float* __restrict__ wt,
                               const float* __restrict__ eout,
                               float* __restrict__ out) {
    int t = blockIdx.x;
    int e0 = expid[t],          s0 = slot[t];          float w0 = wt[t];
    int e1 = expid[N_TOK + t],  s1 = slot[N_TOK + t];  float w1 = wt[N_TOK + t];
    int i = threadIdx.x;
    float4 r = make_float4(0.f, 0.f, 0.f, 0.f);
    if (s0 >= 0) {
        float4 v = ((const float4*)(eout + ((size_t)e0 * CAP + s0) * DIM))[i];
        r.x += w0 * v.x; r.y += w0 * v.y; r.z += w0 * v.z; r.w += w0 * v.w;
    }
    if (s1 >= 0) {
        float4 v = ((const float4*)(eout + ((size_t)e1 * CAP + s1) * DIM))[i];
        r.x += w1 * v.x; r.y += w1 * v.y; r.z += w1 * v.z; r.w += w1 * v.w;
    }
    ((float4*)(out + (size_t)t * DIM))[i] = r;
}

// ---------------- launch ----------------
extern "C" void kernel_launch(void* const* d_in, const int* in_sizes, int n_in,
                              void* d_out, int out_size) {
    const float* x         = (const float*)d_in[0];
    const float* gate_w    = (const float*)d_in[1];
    const float* c_fc      = (const float*)d_in[2];
    const float* fc_bias   = (const float*)d_in[3];
    const float* c_proj    = (const float*)d_in[4];
    const float* proj_bias = (const float*)d_in[5];
    float* out = (float*)d_out;

    float *xbuf, *hbuf, *eout, *wt, *wr1, *wr2;
    int *expid, *slot;
    cudaGetSymbolAddress((void**)&xbuf,  g_xbuf);
    cudaGetSymbolAddress((void**)&hbuf,  g_h);
    cudaGetSymbolAddress((void**)&eout,  g_eout);
    cudaGetSymbolAddress((void**)&wr1,   g_wr1);
    cudaGetSymbolAddress((void**)&wr2,   g_wr2);
    cudaGetSymbolAddress((void**)&expid, g_expid);
    cudaGetSymbolAddress((void**)&slot,  g_slot);
    cudaGetSymbolAddress((void**)&wt,    g_wtp);

    const int smem_bytes = SMEM_W * 4;
    cudaFuncSetAttribute(gemm_cp<true>,  cudaFuncAttributeMaxDynamicSharedMemorySize, smem_bytes);
    cudaFuncSetAttribute(gemm_cp<false>, cudaFuncAttributeMaxDynamicSharedMemorySize, smem_bytes);

    router_kernel<<<N_TOK / 8, 256>>>(x, gate_w, expid, wt);
    assign_kernel<<<1, 256>>>(expid, slot);
    gather_kernel<<<2 * N_TOK, 256>>>(x, expid, slot, xbuf);

    // permute+round weights into B-fragment-major layout
    // blocks per weight tensor: E * (N/8) * (K/16) warps, 8 warps per CTA
    permute_b_kernel<<<(NEXP * (HID / 8) * (DIM / 16)) / 8, 256>>>(c_fc,   wr1, DIM, HID);
    permute_b_kernel<<<(NEXP * (DIM / 8) * (HID / 16)) / 8, 256>>>(c_proj, wr2, HID, DIM);

    // GEMM1 + GELU: [CAP,DIM] x [DIM,HID] -> [CAP,HID]  (output in A'-layout)
    dim3 g1(HID / 128, CAP / 128, NEXP);
    gemm_cp<true><<<g1, 256, smem_bytes>>>(xbuf, wr1, fc_bias, hbuf,
                                           DIM, HID,
                                           (long long)CAP * DIM, (long long)DIM * HID,
                                           (long long)CAP * HID, HID, DIM / 16);

    // GEMM2 + bias: [CAP,HID] x [HID,DIM] -> [CAP,DIM]  (row-major output)
    dim3 g2(DIM / 128, CAP / 128, NEXP);
    gemm_cp<false><<<g2, 256, smem_bytes>>>(hbuf, wr2, proj_bias, eout,
                                            HID, DIM,
                                            (long long)CAP * HID, (long long)HID * DIM,
                                            (long long)CAP * DIM, DIM, HID / 16);

    combine_kernel<<<N_TOK, 256>>>(expid, slot, wt, eout, out);
}

// round 8
// speedup vs baseline: 7.0502x; 1.6508x over previous
#include <cuda_runtime.h>
#include <cuda_fp16.h>
#include <math.h>
#include <stdint.h>

#define N_TOK 4096
#define DIM   1024
#define HID   4096
#define NEXP  8
#define CAP   1280   // int(1.25 * 4096 * 2 / 8)

// ---------------- scratch (static device globals; no allocation) ----------------
// A'-fragment-major (fp16, m16n8k16): block = m16 x k16 = 256 halves = 128 u32 words.
//   word = lane*4 + v, lane = (m&7)*4 + qd, halves (2qd,2qd+1) of k%16,
//   v = ((m>>3)&1) + 2*((k>>3)&1).
// B'-fragment-major (fp16): block = k16 x n8 = 128 halves = 64 u32 words.
//   word = lane*2 + v, lane = (n&7)*4 + qd, halves k = (2qd,2qd+1)+8*v.
__device__ uint32_t g_xbuf[(size_t)NEXP * CAP * DIM / 2];
__device__ uint32_t g_h   [(size_t)NEXP * CAP * HID / 2];
__device__ float    g_eout[(size_t)NEXP * CAP * DIM];
__device__ uint32_t g_wr1 [(size_t)NEXP * DIM * HID / 2];
__device__ uint32_t g_wr2 [(size_t)NEXP * HID * DIM / 2];
__device__ int      g_expid[2 * N_TOK];
__device__ int      g_slot [2 * N_TOK];
__device__ float    g_wtp  [2 * N_TOK];

__device__ __forceinline__ uint32_t smem_to_u32(const void* p) {
    uint32_t a;
    asm("{ .reg .u64 t; cvta.to.shared.u64 t, %1; cvt.u32.u64 %0, t; }" : "=r"(a) : "l"(p));
    return a;
}
#define CP_ASYNC16(dst, src) \
    asm volatile("cp.async.cg.shared.global [%0], [%1], 16;\n" :: "r"(dst), "l"(src))
#define CP_COMMIT() asm volatile("cp.async.commit_group;\n" ::: "memory")
#define CP_WAIT2()  asm volatile("cp.async.wait_group 2;\n" ::: "memory")

__device__ __forceinline__ void mma16(float d[4], const uint4& a, const uint2& b) {
    asm volatile(
        "mma.sync.aligned.m16n8k16.row.col.f32.f16.f16.f32 "
        "{%0,%1,%2,%3},{%4,%5,%6,%7},{%8,%9},{%0,%1,%2,%3};"
        : "+f"(d[0]), "+f"(d[1]), "+f"(d[2]), "+f"(d[3])
        : "r"(a.x), "r"(a.y), "r"(a.z), "r"(a.w), "r"(b.x), "r"(b.y));
}

// ---------------- weight permute+round: W[K,N] fp32 row-major -> B'-fragment fp16 ----------------
// warp handles a k16 x n32 strip (4 B-blocks); coalesced float4 loads via smem staging.
__global__ void permute_b_kernel(const float* __restrict__ W, uint32_t* __restrict__ R,
                                 int K, int N) {
    __shared__ float s[8][16][36];
    int wrp = threadIdx.x >> 5, lane = threadIdx.x & 31;
    int gw = blockIdx.x * 8 + wrp;
    int spe = (K >> 4) * (N >> 5);      // strips per expert
    int e = gw / spe;
    int st = gw - e * spe;
    int n32 = st / (K >> 4);
    int k16 = st - n32 * (K >> 4);
    const float* Wp = W + (size_t)e * K * N + (size_t)(k16 * 16) * N + n32 * 32;
#pragma unroll
    for (int i = 0; i < 4; i++) {
        int idx = i * 32 + lane;
        int row = idx >> 3, c4 = (idx & 7) * 4;
        float4 v = *(const float4*)(Wp + (size_t)row * N + c4);
        s[wrp][row][c4 + 0] = v.x; s[wrp][row][c4 + 1] = v.y;
        s[wrp][row][c4 + 2] = v.z; s[wrp][row][c4 + 3] = v.w;
    }
    __syncwarp();
    int grp = lane >> 2, qd = lane & 3;
    uint32_t* Re = R + (size_t)e * ((size_t)(K >> 4) * (N >> 3)) * 64;
#pragma unroll
    for (int b = 0; b < 4; b++) {
        int n = b * 8 + grp;
        __half2 v0 = __floats2half2_rn(s[wrp][2 * qd][n],     s[wrp][2 * qd + 1][n]);
        __half2 v1 = __floats2half2_rn(s[wrp][2 * qd + 8][n], s[wrp][2 * qd + 9][n]);
        uint2 o;
        o.x = *(uint32_t*)&v0;
        o.y = *(uint32_t*)&v1;
        size_t blk = (size_t)(n32 * 4 + b) * (K >> 4) + k16;
        *(uint2*)(Re + blk * 64 + lane * 2) = o;
    }
}

// ---------------- router ----------------
__global__ void router_kernel(const float* __restrict__ x,
                              const float* __restrict__ gw,
                              int* __restrict__ expid,
                              float* __restrict__ wt) {
    int warp = threadIdx.x >> 5, lane = threadIdx.x & 31;
    int t = blockIdx.x * 8 + warp;
    if (t >= N_TOK) return;
    const float* xr = x + (size_t)t * DIM;
    float acc[8] = {0.f,0.f,0.f,0.f,0.f,0.f,0.f,0.f};
    for (int d = lane; d < DIM; d += 32) {
        float xv = xr[d];
        const float4* g4 = (const float4*)(gw + (size_t)d * NEXP);
        float4 a = g4[0], b = g4[1];
        acc[0] += xv * a.x; acc[1] += xv * a.y; acc[2] += xv * a.z; acc[3] += xv * a.w;
        acc[4] += xv * b.x; acc[5] += xv * b.y; acc[6] += xv * b.z; acc[7] += xv * b.w;
    }
#pragma unroll
    for (int e = 0; e < 8; e++)
#pragma unroll
        for (int o = 16; o; o >>= 1) acc[e] += __shfl_xor_sync(0xffffffffu, acc[e], o);
    if (lane == 0) {
        int i0 = 0; float l0 = acc[0];
#pragma unroll
        for (int e = 1; e < 8; e++) if (acc[e] > l0) { l0 = acc[e]; i0 = e; }
        int i1 = -1; float l1 = -INFINITY;
#pragma unroll
        for (int e = 0; e < 8; e++) if (e != i0 && acc[e] > l1) { l1 = acc[e]; i1 = e; }
        float z  = expf(l1 - l0);
        float p0 = 1.0f / (1.0f + z);
        expid[t]         = i0;
        expid[N_TOK + t] = i1;
        wt[t]            = p0;
        wt[N_TOK + t]    = z * p0;
    }
}

// ---------------- deterministic slot assignment ----------------
__global__ void assign_kernel(const int* __restrict__ expid, int* __restrict__ slot) {
    __shared__ int counters[NEXP];
    __shared__ int warp_hist[8][NEXP];
    int tid = threadIdx.x, lane = tid & 31, warp = tid >> 5;
    if (tid < NEXP) counters[tid] = 0;
    __syncthreads();
    for (int a = 0; a < 2 * N_TOK; a += 256) {
        int idx = a + tid;
        int e = expid[idx];
        unsigned peers = __match_any_sync(0xffffffffu, e);
        int rank = __popc(peers & ((1u << lane) - 1u));
        if (tid < 64) ((int*)warp_hist)[tid] = 0;
        __syncthreads();
        if (rank == 0) warp_hist[warp][e] = __popc(peers);
        __syncthreads();
        int base = counters[e];
#pragma unroll
        for (int w = 0; w < 8; w++) if (w < warp) base += warp_hist[w][e];
        int s = base + rank;
        slot[idx] = (s < CAP) ? s : -1;
        __syncthreads();
        if (tid < NEXP) {
            int c = counters[tid];
#pragma unroll
            for (int w = 0; w < 8; w++) c += warp_hist[w][tid];
            counters[tid] = c;
        }
        __syncthreads();
    }
}

// ---------------- gather: x row -> A'-fragment fp16 ----------------
__global__ void gather_kernel(const float* __restrict__ x,
                              const int* __restrict__ expid,
                              const int* __restrict__ slot,
                              uint32_t* __restrict__ xbuf) {
    int a = blockIdx.x;
    int s = slot[a];
    if (s < 0) return;
    int e = expid[a];
    int t = a & (N_TOK - 1);
    int tid = threadIdx.x;
    float4 v = ((const float4*)(x + (size_t)t * DIM))[tid];
    int r = s & 15;
    __half2 h0 = __floats2half2_rn(v.x, v.y);
    __half2 h1 = __floats2half2_rn(v.z, v.w);
    uint32_t* base = xbuf + (size_t)e * (CAP * DIM / 2)
                   + ((size_t)(s >> 4) * (DIM >> 4) + (tid >> 2)) * 128
                   + ((r & 7) * 4 + 2 * (tid & 1)) * 4 + (r >> 3) + 2 * ((tid >> 1) & 1);
    base[0] = *(uint32_t*)&h0;
    base[4] = *(uint32_t*)&h1;
}

// ============ fp16 mma.sync m16n8k16 GEMM, fragment-major A and B ============
// Block tile 128x128, ktile 16, 8 warps of 64x32, 4-stage cp.async.
// Smem per stage: A = 8 blocks x 512B = 4KB, B = 16 blocks x 256B = 4KB.
#define A_STAGE_W 1024   // u32 words
#define B_STAGE_W 1024
#define SMEM_W    (4 * (A_STAGE_W + B_STAGE_W))   // 8192 words = 32768 B

// AOUT: write C in A'-fragment fp16 (for next GEMM) + exact GELU; else fp32 row-major.
template <bool AOUT>
__global__ void __launch_bounds__(256, 2)
gemm_fp16(const uint32_t* __restrict__ A, const uint32_t* __restrict__ B,
          const float* __restrict__ bias, void* __restrict__ Cv,
          int ldc, long long sA, long long sB, long long sC, int sBias, int NK) {
    extern __shared__ __align__(16) uint32_t smemU[];
    const uint32_t sbase = smem_to_u32(smemU);

    const int e = blockIdx.z;
    A    += (size_t)e * sA;
    B    += (size_t)e * sB;
    bias += (size_t)e * sBias;
    const int m0 = blockIdx.y * 128, n0 = blockIdx.x * 128;

    const int tid = threadIdx.x, lane = tid & 31, wid = tid >> 5;
    const int wm16 = (wid & 1) * 4;       // m16-block offset
    const int wn = (wid >> 1) * 32;
    const int grp = lane >> 2, qd = lane & 3;

    // A cp.async: blkT = m16 block (0..7), laneT = 16B chunk (0..31)
    const int laneT = tid & 31, blkT = tid >> 5;
    const uint32_t* srcA = A + ((size_t)((m0 >> 4) + blkT) * NK) * 128 + laneT * 4;
    const uint32_t dstA = sbase + (uint32_t)(blkT * 512 + laneT * 16);

    // B cp.async: blkB = n8 block (0..15), 16B chunk (0..15)
    const int blkB = tid >> 4, fB = (tid & 15) * 4;
    const uint32_t* srcB = B + ((size_t)((n0 >> 3) + blkB) * NK) * 64 + fB;
    const uint32_t dstB = sbase + (uint32_t)(4 * A_STAGE_W * 4) + (uint32_t)(blkB * 256 + fB * 4);

#define CPAB(kt, st)                                                         \
    do {                                                                     \
        CP_ASYNC16(dstA + (uint32_t)((st) * (A_STAGE_W * 4)),                \
                   srcA + (size_t)(kt) * 128);                               \
        CP_ASYNC16(dstB + (uint32_t)((st) * (B_STAGE_W * 4)),                \
                   srcB + (size_t)(kt) * 64);                                \
    } while (0)

    float acc[4][4][4];
#pragma unroll
    for (int i = 0; i < 4; i++)
#pragma unroll
        for (int j = 0; j < 4; j++)
#pragma unroll
            for (int r = 0; r < 4; r++) acc[i][j][r] = 0.f;

#define COMPUTE(st)                                                          \
    do {                                                                     \
        const uint32_t* aS = smemU + (st) * A_STAGE_W;                       \
        const uint32_t* bS = smemU + 4 * A_STAGE_W + (st) * B_STAGE_W;       \
        uint2 b[4]; uint4 a[4];                                              \
        _Pragma("unroll") for (int nt = 0; nt < 4; nt++)                     \
            b[nt] = *(const uint2*)(bS + ((wn >> 3) + nt) * 64 + lane * 2);  \
        _Pragma("unroll") for (int mt = 0; mt < 4; mt++)                     \
            a[mt] = *(const uint4*)(aS + (wm16 + mt) * 128 + lane * 4);      \
        _Pragma("unroll") for (int mt = 0; mt < 4; mt++)                     \
            _Pragma("unroll") for (int nt = 0; nt < 4; nt++)                 \
                mma16(acc[mt][nt], a[mt], b[nt]);                            \
    } while (0)

#define ITER(kt, st)                                                         \
    do {                                                                     \
        CP_WAIT2();                                                          \
        __syncthreads();                                                     \
        COMPUTE(st);                                                         \
        if ((kt) + 3 < NK) CPAB((kt) + 3, ((st) + 3) & 3);                   \
        CP_COMMIT();                                                         \
    } while (0)

    CPAB(0, 0); CP_COMMIT();
    CPAB(1, 1); CP_COMMIT();
    CPAB(2, 2); CP_COMMIT();

    for (int kt4 = 0; kt4 < NK; kt4 += 4) {
        ITER(kt4 + 0, 0);
        ITER(kt4 + 1, 1);
        ITER(kt4 + 2, 2);
        ITER(kt4 + 3, 3);
    }
#undef CPAB
#undef COMPUTE
#undef ITER

    // ---- epilogue ----
#pragma unroll
    for (int mt = 0; mt < 4; mt++) {
#pragma unroll
        for (int nt = 0; nt < 4; nt++) {
            int col = n0 + wn + nt * 8 + qd * 2;
            float b0 = bias[col], b1 = bias[col + 1];
#pragma unroll
            for (int h = 0; h < 2; h++) {
                float v0 = acc[mt][nt][h * 2 + 0] + b0;
                float v1 = acc[mt][nt][h * 2 + 1] + b1;
                if (AOUT) {
                    v0 = 0.5f * v0 * (1.0f + erff(v0 * 0.70710678118654752f));
                    v1 = 0.5f * v1 * (1.0f + erff(v1 * 0.70710678118654752f));
                    size_t row16 = (size_t)((m0 >> 4) + wm16 + mt);
                    int col16 = ((n0 + wn) >> 4) + (nt >> 1);
                    uint32_t* cw = (uint32_t*)Cv + (size_t)e * sC
                                 + (row16 * (ldc >> 4) + col16) * 128
                                 + lane * 4 + 2 * (nt & 1);
                    __half2 hv = __floats2half2_rn(v0, v1);
                    cw[h] = *(uint32_t*)&hv;
                } else {
                    float* C = (float*)Cv + (size_t)e * sC;
                    size_t row = (size_t)(m0 + (wm16 << 4) + mt * 16 + grp + h * 8);
                    *(float2*)(C + row * ldc + col) = make_float2(v0, v1);
                }
            }
        }
    }
}

// ---------------- combine ----------------
__global__ void combine_kernel(const int* __restrict__ expid,
                               const int* __restrict__ slot,
                               const float* __restrict__ wt,
                               const float* __restrict__ eout,
                               float* __restrict__ out) {
    int t = blockIdx.x;
    int e0 = expid[t],          s0 = slot[t];          float w0 = wt[t];
    int e1 = expid[N_TOK + t],  s1 = slot[N_TOK + t];  float w1 = wt[N_TOK + t];
    int i = threadIdx.x;
    float4 r = make_float4(0.f, 0.f, 0.f, 0.f);
    if (s0 >= 0) {
        float4 v = ((const float4*)(eout + ((size_t)e0 * CAP + s0) * DIM))[i];
        r.x += w0 * v.x; r.y += w0 * v.y; r.z += w0 * v.z; r.w += w0 * v.w;
    }
    if (s1 >= 0) {
        float4 v = ((const float4*)(eout + ((size_t)e1 * CAP + s1) * DIM))[i];
        r.x += w1 * v.x; r.y += w1 * v.y; r.z += w1 * v.z; r.w += w1 * v.w;
    }
    ((float4*)(out + (size_t)t * DIM))[i] = r;
}

// ---------------- launch ----------------
extern "C" void kernel_launch(void* const* d_in, const int* in_sizes, int n_in,
                              void* d_out, int out_size) {
    const float* x         = (const float*)d_in[0];
    const float* gate_w    = (const float*)d_in[1];
    const float* c_fc      = (const float*)d_in[2];
    const float* fc_bias   = (const float*)d_in[3];
    const float* c_proj    = (const float*)d_in[4];
    const float* proj_bias = (const float*)d_in[5];
    float* out = (float*)d_out;

    uint32_t *xbuf, *hbuf, *wr1, *wr2;
    float *eout, *wt;
    int *expid, *slot;
    cudaGetSymbolAddress((void**)&xbuf,  g_xbuf);
    cudaGetSymbolAddress((void**)&hbuf,  g_h);
    cudaGetSymbolAddress((void**)&eout,  g_eout);
    cudaGetSymbolAddress((void**)&wr1,   g_wr1);
    cudaGetSymbolAddress((void**)&wr2,   g_wr2);
    cudaGetSymbolAddress((void**)&expid, g_expid);
    cudaGetSymbolAddress((void**)&slot,  g_slot);
    cudaGetSymbolAddress((void**)&wt,    g_wtp);

    const int smem_bytes = SMEM_W * 4;
    cudaFuncSetAttribute(gemm_fp16<true>,  cudaFuncAttributeMaxDynamicSharedMemorySize, smem_bytes);
    cudaFuncSetAttribute(gemm_fp16<false>, cudaFuncAttributeMaxDynamicSharedMemorySize, smem_bytes);

    router_kernel<<<N_TOK / 8, 256>>>(x, gate_w, expid, wt);
    assign_kernel<<<1, 256>>>(expid, slot);
    gather_kernel<<<2 * N_TOK, 256>>>(x, expid, slot, xbuf);

    // permute+round weights -> B'-fragment fp16 (strips: E*(K/16)*(N/32), 8 warps/CTA)
    permute_b_kernel<<<(NEXP * (DIM / 16) * (HID / 32)) / 8, 256>>>(c_fc,   wr1, DIM, HID);
    permute_b_kernel<<<(NEXP * (HID / 16) * (DIM / 32)) / 8, 256>>>(c_proj, wr2, HID, DIM);

    // GEMM1 + GELU: [CAP,DIM] x [DIM,HID] -> [CAP,HID] (A'-fragment fp16 out)
    dim3 g1(HID / 128, CAP / 128, NEXP);
    gemm_fp16<true><<<g1, 256, smem_bytes>>>(xbuf, wr1, fc_bias, hbuf,
                                             HID,
                                             (long long)CAP * DIM / 2, (long long)DIM * HID / 2,
                                             (long long)CAP * HID / 2, HID, DIM / 16);

    // GEMM2 + bias: [CAP,HID] x [HID,DIM] -> [CAP,DIM] (fp32 row-major out)
    dim3 g2(DIM / 128, CAP / 128, NEXP);
    gemm_fp16<false><<<g2, 256, smem_bytes>>>(hbuf, wr2, proj_bias, eout,
                                              DIM,
                                              (long long)CAP * HID / 2, (long long)HID * DIM / 2,
                                              (long long)CAP * DIM, DIM, HID / 16);

    combine_kernel<<<N_TOK, 256>>>(expid, slot, wt, eout, out);
}